// round 5
// baseline (speedup 1.0000x reference)
#include <cuda_runtime.h>
#include <cuda_bf16.h>
#include <math.h>
#include <cstdint>

#define D_MODEL 2048
#define NHEADS  16
#define DK      128
#define BATCH   2
#define SEQ     2048
#define ROWS    (BATCH * SEQ)     // 4096
#define QKV_N   (3 * D_MODEL)     // 6144

// ---------------------------------------------------------------------------
// Scratch (device globals — no cudaMalloc allowed)
// ---------------------------------------------------------------------------
__device__ __nv_bfloat16 g_qkv_hi[ROWS * QKV_N];
__device__ __nv_bfloat16 g_qkv_lo[ROWS * QKV_N];
__device__ __nv_bfloat16 g_a_hi[ROWS * D_MODEL];
__device__ __nv_bfloat16 g_a_lo[ROWS * D_MODEL];
__device__ __nv_bfloat16 g_wq_hi[QKV_N * D_MODEL];
__device__ __nv_bfloat16 g_wq_lo[QKV_N * D_MODEL];
__device__ __nv_bfloat16 g_wo_hi[D_MODEL * D_MODEL];
__device__ __nv_bfloat16 g_wo_lo[D_MODEL * D_MODEL];

// ---------------------------------------------------------------------------
// Base-target PTX helpers (virtual target is compute_103 — no tcgen05)
// ---------------------------------------------------------------------------
__device__ __forceinline__ uint32_t smem_u32(const void* p) {
    uint32_t a;
    asm("{ .reg .u64 t; cvta.to.shared.u64 t, %1; cvt.u32.u64 %0, t; }" : "=r"(a) : "l"(p));
    return a;
}
__device__ __forceinline__ void cp_async16(uint32_t saddr, const void* gaddr) {
    asm volatile("cp.async.cg.shared.global [%0], [%1], 16;" :: "r"(saddr), "l"(gaddr));
}
#define CP_COMMIT() asm volatile("cp.async.commit_group;" ::: "memory")
#define CP_WAIT(N)  asm volatile("cp.async.wait_group %0;" :: "n"(N) : "memory")

__device__ __forceinline__ void ldmx4(uint32_t* r, uint32_t addr) {
    asm volatile("ldmatrix.sync.aligned.m8n8.x4.shared.b16 {%0,%1,%2,%3}, [%4];"
                 : "=r"(r[0]), "=r"(r[1]), "=r"(r[2]), "=r"(r[3]) : "r"(addr));
}
__device__ __forceinline__ void ldmx4t(uint32_t* r, uint32_t addr) {
    asm volatile("ldmatrix.sync.aligned.m8n8.x4.trans.shared.b16 {%0,%1,%2,%3}, [%4];"
                 : "=r"(r[0]), "=r"(r[1]), "=r"(r[2]), "=r"(r[3]) : "r"(addr));
}
__device__ __forceinline__ void mma_bf16(float* d, const uint32_t* a, const uint32_t* b) {
    asm volatile(
        "mma.sync.aligned.m16n8k16.row.col.f32.bf16.bf16.f32 "
        "{%0,%1,%2,%3}, {%4,%5,%6,%7}, {%8,%9}, {%0,%1,%2,%3};"
        : "+f"(d[0]), "+f"(d[1]), "+f"(d[2]), "+f"(d[3])
        : "r"(a[0]), "r"(a[1]), "r"(a[2]), "r"(a[3]), "r"(b[0]), "r"(b[1]));
}

__device__ __forceinline__ void split2(float x, float y, uint32_t& h, uint32_t& l) {
    __nv_bfloat16 hx = __float2bfloat16(x), hy = __float2bfloat16(y);
    __nv_bfloat16 lx = __float2bfloat16(x - __bfloat162float(hx));
    __nv_bfloat16 ly = __float2bfloat16(y - __bfloat162float(hy));
    __nv_bfloat162 hh = __halves2bfloat162(hx, hy);
    __nv_bfloat162 ll = __halves2bfloat162(lx, ly);
    h = *(uint32_t*)&hh;
    l = *(uint32_t*)&ll;
}

__device__ __forceinline__ uint32_t sw_off(int r, int c) {
    return (uint32_t)(r * 64 + ((c ^ ((r >> 1) & 3)) << 4));
}
__device__ __forceinline__ uint32_t asw(int row, int ch) {
    return (uint32_t)(row * 256 + ((ch ^ (row & 7)) << 4));
}

// ---------------------------------------------------------------------------
__global__ void split_kernel(const float* __restrict__ in,
                             __nv_bfloat16* __restrict__ hi,
                             __nv_bfloat16* __restrict__ lo, int n4)
{
    int i = blockIdx.x * blockDim.x + threadIdx.x;
    if (i >= n4) return;
    float4 v = ((const float4*)in)[i];
    uint32_t h0, l0, h1, l1;
    split2(v.x, v.y, h0, l0);
    split2(v.z, v.w, h1, l1);
    ((uint32_t*)hi)[2*i]   = h0;
    ((uint32_t*)hi)[2*i+1] = h1;
    ((uint32_t*)lo)[2*i]   = l0;
    ((uint32_t*)lo)[2*i+1] = l1;
}

__global__ void transpose_split_kernel(const float* __restrict__ W,
                                       __nv_bfloat16* __restrict__ Th,
                                       __nv_bfloat16* __restrict__ Tl,
                                       int K, int N)
{
    __shared__ float t[32][33];
    int k0 = blockIdx.y * 32, n0 = blockIdx.x * 32;
    #pragma unroll
    for (int i = threadIdx.y; i < 32; i += 8)
        t[i][threadIdx.x] = W[(size_t)(k0 + i) * N + n0 + threadIdx.x];
    __syncthreads();
    #pragma unroll
    for (int i = threadIdx.y; i < 32; i += 8) {
        float v = t[threadIdx.x][i];
        __nv_bfloat16 h = __float2bfloat16(v);
        __nv_bfloat16 l = __float2bfloat16(v - __bfloat162float(h));
        size_t o = (size_t)(n0 + i) * K + k0 + threadIdx.x;
        Th[o] = h;
        Tl[o] = l;
    }
}

// ---------------------------------------------------------------------------
// HMMA GEMM: single barrier per K-iter, loads issued before compute.
// ---------------------------------------------------------------------------
#define GM_BK    32
#define STAGES   3
#define TILE_B   8192
#define STAGE_B  (4 * TILE_B)
#define GEMM_SMEM (STAGES * STAGE_B)        // 96 KB
#define OFF_AH 0
#define OFF_AL TILE_B
#define OFF_BH (2 * TILE_B)
#define OFF_BL (3 * TILE_B)

template<bool SPLIT>
__global__ __launch_bounds__(256) void gemm_hmma(
    const __nv_bfloat16* __restrict__ Ah, const __nv_bfloat16* __restrict__ Al,
    const __nv_bfloat16* __restrict__ Bh, const __nv_bfloat16* __restrict__ Bl,
    const float* __restrict__ bias, float* __restrict__ C,
    __nv_bfloat16* __restrict__ Ch, __nv_bfloat16* __restrict__ Cl,
    int M, int N, int K)
{
    extern __shared__ char smc[];
    const uint32_t sb = smem_u32(smc);
    const int tid  = threadIdx.x;
    const int warp = tid >> 5, lane = tid & 31;
    const int wm = warp >> 1, wn = warp & 1;
    const int bm = blockIdx.y, bn = blockIdx.x;
    const int NC = K / GM_BK;

    const __nv_bfloat16* gAh = Ah + (size_t)bm * 128 * K;
    const __nv_bfloat16* gAl = Al + (size_t)bm * 128 * K;
    const __nv_bfloat16* gBh = Bh + (size_t)bn * 128 * K;
    const __nv_bfloat16* gBl = Bl + (size_t)bn * 128 * K;

    const int r0 = tid >> 2, c0 = tid & 3;

    auto load_stage = [&](int chunk, int slot) {
        const int k0 = chunk * GM_BK;
        uint32_t base = sb + slot * STAGE_B;
        #pragma unroll
        for (int i = 0; i < 2; i++) {
            int r = r0 + i * 64;
            uint32_t so = sw_off(r, c0);
            size_t go = (size_t)r * K + k0 + c0 * 8;
            cp_async16(base + OFF_AH + so, gAh + go);
            cp_async16(base + OFF_AL + so, gAl + go);
            cp_async16(base + OFF_BH + so, gBh + go);
            cp_async16(base + OFF_BL + so, gBl + go);
        }
        CP_COMMIT();
    };

    float acc[2][8][4];
    #pragma unroll
    for (int mt = 0; mt < 2; mt++)
        #pragma unroll
        for (int nt = 0; nt < 8; nt++)
            #pragma unroll
            for (int j = 0; j < 4; j++) acc[mt][nt][j] = 0.f;

    const int a_row = wm * 32 + (lane & 15);
    const int a_cb  = (lane >> 4) & 1;
    const int b_row = wn * 64 + (lane & 7) + ((lane & 16) ? 8 : 0);
    const int b_cb  = (lane >> 3) & 1;

    #pragma unroll
    for (int s = 0; s < STAGES - 1; s++) load_stage(s, s);

    for (int c = 0; c < NC; c++) {
        if (c + STAGES - 1 < NC) { CP_WAIT(STAGES - 2); }
        else                     { CP_WAIT(0); }
        __syncthreads();
        // issue next stage's loads BEFORE compute (slot was last read in iter
        // c-1; every warp passed the barrier above, so reuse is safe)
        if (c + STAGES - 1 < NC) load_stage(c + STAGES - 1, (c + STAGES - 1) % STAGES);

        const uint32_t base = sb + (c % STAGES) * STAGE_B;

        #pragma unroll
        for (int ks = 0; ks < 2; ks++) {
            uint32_t ahf[2][4], alf[2][4];
            #pragma unroll
            for (int mt = 0; mt < 2; mt++) {
                uint32_t so = sw_off(a_row + mt * 16, 2 * ks + a_cb);
                ldmx4(ahf[mt], base + OFF_AH + so);
                ldmx4(alf[mt], base + OFF_AL + so);
            }
            uint32_t bhf[8][2], blf[8][2];
            #pragma unroll
            for (int p = 0; p < 4; p++) {
                uint32_t so = sw_off(b_row + p * 16, 2 * ks + b_cb);
                uint32_t r[4];
                ldmx4(r, base + OFF_BH + so);
                bhf[2*p][0] = r[0]; bhf[2*p][1] = r[1];
                bhf[2*p+1][0] = r[2]; bhf[2*p+1][1] = r[3];
                ldmx4(r, base + OFF_BL + so);
                blf[2*p][0] = r[0]; blf[2*p][1] = r[1];
                blf[2*p+1][0] = r[2]; blf[2*p+1][1] = r[3];
            }
            #pragma unroll
            for (int mt = 0; mt < 2; mt++)
                #pragma unroll
                for (int nt = 0; nt < 8; nt++) {
                    mma_bf16(acc[mt][nt], ahf[mt], bhf[nt]);
                    mma_bf16(acc[mt][nt], ahf[mt], blf[nt]);
                    mma_bf16(acc[mt][nt], alf[mt], bhf[nt]);
                }
        }
        // no trailing barrier: next iteration's top barrier covers the hazard
    }

    const int erow = bm * 128 + wm * 32 + (lane >> 2);
    const int ecol = bn * 128 + wn * 64 + (lane & 3) * 2;
    #pragma unroll
    for (int mt = 0; mt < 2; mt++)
        #pragma unroll
        for (int nt = 0; nt < 8; nt++) {
            int col = ecol + nt * 8;
            float bx = bias[col], by = bias[col + 1];
            int ra = erow + mt * 16, rb = ra + 8;
            float v0 = acc[mt][nt][0] + bx, v1 = acc[mt][nt][1] + by;
            float v2 = acc[mt][nt][2] + bx, v3 = acc[mt][nt][3] + by;
            if (SPLIT) {
                uint32_t hh, ll;
                split2(v0, v1, hh, ll);
                *(uint32_t*)&Ch[(size_t)ra * N + col] = hh;
                *(uint32_t*)&Cl[(size_t)ra * N + col] = ll;
                split2(v2, v3, hh, ll);
                *(uint32_t*)&Ch[(size_t)rb * N + col] = hh;
                *(uint32_t*)&Cl[(size_t)rb * N + col] = ll;
            } else {
                float2 o0 = {v0, v1}, o1 = {v2, v3};
                *(float2*)&C[(size_t)ra * N + col] = o0;
                *(float2*)&C[(size_t)rb * N + col] = o1;
            }
        }
}

// ---------------------------------------------------------------------------
// HMMA flash attention. 1 CTA/SM (192 KB smem) -> 256-reg budget:
// Q fragments hoisted into registers; prefetches issued before compute.
// ---------------------------------------------------------------------------
#define AT_BQ 128
#define AT_BK 64
#define AT_NT (SEQ / AT_BK)          // 32
#define AQ_H 0
#define AQ_L 32768
#define AST(s) (65536 + (s) * 65536)
#define AK_H 0
#define AK_L 16384
#define AV_H 32768
#define AV_L 49152
#define ATTN_SMEM (65536 + 2 * 65536)   // 192 KB

__global__ __launch_bounds__(256, 1) void attn_hmma(
    const __nv_bfloat16* __restrict__ qh_g, const __nv_bfloat16* __restrict__ ql_g,
    __nv_bfloat16* __restrict__ oh_g, __nv_bfloat16* __restrict__ ol_g)
{
    extern __shared__ char smc[];
    const uint32_t sb = smem_u32(smc);
    const int tid = threadIdx.x, warp = tid >> 5, lane = tid & 31;
    const int qt = blockIdx.x, bh = blockIdx.y;
    const int b = bh >> 4, h = bh & 15;
    const size_t tok0  = (size_t)b * SEQ + qt * AT_BQ;
    const size_t ktok0 = (size_t)b * SEQ;
    const int colQ = h * 3 * DK, colK = colQ + DK, colV = colQ + 2 * DK;
    const float SCALE = 0.08838834764831845f;

    auto loadQ = [&]() {
        #pragma unroll
        for (int i = 0; i < 8; i++) {
            int idx = tid + i * 256;
            int r = idx >> 4, ch = idx & 15;
            uint32_t so = asw(r, ch);
            size_t g = (tok0 + r) * QKV_N + colQ + ch * 8;
            cp_async16(sb + AQ_H + so, qh_g + g);
            cp_async16(sb + AQ_L + so, ql_g + g);
        }
        CP_COMMIT();
    };
    auto loadK = [&](int kt, int s) {
        #pragma unroll
        for (int i = 0; i < 4; i++) {
            int idx = tid + i * 256;
            int r = idx >> 4, ch = idx & 15;
            uint32_t so = asw(r, ch);
            size_t g = (ktok0 + kt * AT_BK + r) * QKV_N + colK + ch * 8;
            cp_async16(sb + AST(s) + AK_H + so, qh_g + g);
            cp_async16(sb + AST(s) + AK_L + so, ql_g + g);
        }
        CP_COMMIT();
    };
    auto loadV = [&](int kt, int s) {
        #pragma unroll
        for (int i = 0; i < 4; i++) {
            int idx = tid + i * 256;
            int r = idx >> 4, ch = idx & 15;
            uint32_t so = asw(r, ch);
            size_t g = (ktok0 + kt * AT_BK + r) * QKV_N + colV + ch * 8;
            cp_async16(sb + AST(s) + AV_H + so, qh_g + g);
            cp_async16(sb + AST(s) + AV_L + so, ql_g + g);
        }
        CP_COMMIT();
    };

    const int aq_row = warp * 16 + (lane & 15);
    const int a_cb   = lane >> 4;
    const int bk_row = (lane & 7) + ((lane & 16) ? 8 : 0);
    const int bk_cb  = (lane >> 3) & 1;
    const int v_row  = (lane & 7) + (((lane >> 3) & 1) << 3);
    const int v_cb   = lane >> 4;

    float oacc[16][4];
    #pragma unroll
    for (int n = 0; n < 16; n++)
        #pragma unroll
        for (int j = 0; j < 4; j++) oacc[n][j] = 0.f;
    float m0 = -1e30f, m1 = -1e30f, l0 = 0.f, l1 = 0.f;

    // prologue: Q, K0, V0, K1
    loadQ();
    loadK(0, 0);
    loadV(0, 0);
    loadK(1, 1);

    // hoist Q fragments into registers (Q smem never re-read afterwards)
    CP_WAIT(3);                     // Q complete
    __syncthreads();
    uint32_t qfh[8][4], qfl[8][4];
    #pragma unroll
    for (int ks = 0; ks < 8; ks++) {
        uint32_t qso = asw(aq_row, 2 * ks + a_cb);
        ldmx4(qfh[ks], sb + AQ_H + qso);
        ldmx4(qfl[ks], sb + AQ_L + qso);
    }

    for (int kt = 0; kt < AT_NT; kt++) {
        const int cur = kt & 1;

        CP_WAIT(2);              // K_kt complete
        __syncthreads();
        // prefetch next V first (slot cur^1 V was last read in iter kt-1)
        loadV((kt + 1) % AT_NT, cur ^ 1);

        const uint32_t kb = sb + AST(cur);

        // ---- S = Q K^T (3 products) ----
        float sacc[8][4];
        #pragma unroll
        for (int n = 0; n < 8; n++)
            #pragma unroll
            for (int j = 0; j < 4; j++) sacc[n][j] = 0.f;

        #pragma unroll
        for (int ks = 0; ks < 8; ks++) {
            #pragma unroll
            for (int p = 0; p < 4; p++) {
                uint32_t kh4[4], kl4[4];
                uint32_t kso = asw(p * 16 + bk_row, 2 * ks + bk_cb);
                ldmx4(kh4, kb + AK_H + kso);
                ldmx4(kl4, kb + AK_L + kso);
                mma_bf16(sacc[2*p],   qfh[ks], kh4);
                mma_bf16(sacc[2*p+1], qfh[ks], kh4 + 2);
                mma_bf16(sacc[2*p],   qfh[ks], kl4);
                mma_bf16(sacc[2*p+1], qfh[ks], kl4 + 2);
                mma_bf16(sacc[2*p],   qfl[ks], kh4);
                mma_bf16(sacc[2*p+1], qfl[ks], kh4 + 2);
            }
        }

        // ---- online softmax ----
        float mx0 = -1e30f, mx1 = -1e30f;
        #pragma unroll
        for (int n = 0; n < 8; n++) {
            sacc[n][0] *= SCALE; sacc[n][1] *= SCALE;
            sacc[n][2] *= SCALE; sacc[n][3] *= SCALE;
            mx0 = fmaxf(mx0, fmaxf(sacc[n][0], sacc[n][1]));
            mx1 = fmaxf(mx1, fmaxf(sacc[n][2], sacc[n][3]));
        }
        mx0 = fmaxf(mx0, __shfl_xor_sync(0xffffffffu, mx0, 1));
        mx0 = fmaxf(mx0, __shfl_xor_sync(0xffffffffu, mx0, 2));
        mx1 = fmaxf(mx1, __shfl_xor_sync(0xffffffffu, mx1, 1));
        mx1 = fmaxf(mx1, __shfl_xor_sync(0xffffffffu, mx1, 2));
        const float mn0 = fmaxf(m0, mx0), mn1 = fmaxf(m1, mx1);

        float sum0 = 0.f, sum1 = 0.f;
        uint32_t ph[8][2], pl[8][2];
        #pragma unroll
        for (int n = 0; n < 8; n++) {
            float p00 = __expf(sacc[n][0] - mn0), p01 = __expf(sacc[n][1] - mn0);
            float p10 = __expf(sacc[n][2] - mn1), p11 = __expf(sacc[n][3] - mn1);
            sum0 += p00 + p01;
            sum1 += p10 + p11;
            split2(p00, p01, ph[n][0], pl[n][0]);
            split2(p10, p11, ph[n][1], pl[n][1]);
        }
        sum0 += __shfl_xor_sync(0xffffffffu, sum0, 1);
        sum0 += __shfl_xor_sync(0xffffffffu, sum0, 2);
        sum1 += __shfl_xor_sync(0xffffffffu, sum1, 1);
        sum1 += __shfl_xor_sync(0xffffffffu, sum1, 2);

        const float al0 = __expf(m0 - mn0), al1 = __expf(m1 - mn1);
        m0 = mn0; m1 = mn1;
        l0 = l0 * al0 + sum0;
        l1 = l1 * al1 + sum1;
        #pragma unroll
        for (int n = 0; n < 16; n++) {
            oacc[n][0] *= al0; oacc[n][1] *= al0;
            oacc[n][2] *= al1; oacc[n][3] *= al1;
        }

        CP_WAIT(2);              // V_kt complete
        __syncthreads();
        // prefetch K two tiles ahead first (slot cur K was last read by this
        // iteration's S, complete before the barrier above)
        loadK((kt + 2) % AT_NT, cur);

        const uint32_t vb = sb + AST(cur);

        // ---- O += P V (3 products) ----
        #pragma unroll
        for (int kk = 0; kk < 4; kk++) {
            uint32_t pah[4] = {ph[2*kk][0], ph[2*kk][1], ph[2*kk+1][0], ph[2*kk+1][1]};
            uint32_t pal[4] = {pl[2*kk][0], pl[2*kk][1], pl[2*kk+1][0], pl[2*kk+1][1]};
            #pragma unroll
            for (int p = 0; p < 8; p++) {
                uint32_t vh4[4], vl4[4];
                uint32_t vso = asw(kk * 16 + v_row, 2 * p + v_cb);
                ldmx4t(vh4, vb + AV_H + vso);
                ldmx4t(vl4, vb + AV_L + vso);
                mma_bf16(oacc[2*p],   pah, vh4);
                mma_bf16(oacc[2*p+1], pah, vh4 + 2);
                mma_bf16(oacc[2*p],   pah, vl4);
                mma_bf16(oacc[2*p+1], pah, vl4 + 2);
                mma_bf16(oacc[2*p],   pal, vh4);
                mma_bf16(oacc[2*p+1], pal, vh4 + 2);
            }
        }
    }

    // ---- epilogue ----
    const float inv0 = 1.f / l0, inv1 = 1.f / l1;
    const int rr = lane >> 2, c2 = (lane & 3) * 2;
    const size_t row0 = tok0 + warp * 16 + rr, row1 = row0 + 8;
    #pragma unroll
    for (int n = 0; n < 16; n++) {
        int col = h * DK + n * 8 + c2;
        uint32_t hh, ll;
        split2(oacc[n][0] * inv0, oacc[n][1] * inv0, hh, ll);
        *(uint32_t*)&oh_g[row0 * D_MODEL + col] = hh;
        *(uint32_t*)&ol_g[row0 * D_MODEL + col] = ll;
        split2(oacc[n][2] * inv1, oacc[n][3] * inv1, hh, ll);
        *(uint32_t*)&oh_g[row1 * D_MODEL + col] = hh;
        *(uint32_t*)&ol_g[row1 * D_MODEL + col] = ll;
    }
}

// ---------------------------------------------------------------------------
extern "C" void kernel_launch(void* const* d_in, const int* in_sizes, int n_in,
                              void* d_out, int out_size)
{
    const float* x    = (const float*)d_in[0];
    const float* Wqkv = (const float*)d_in[1];
    const float* bqkv = (const float*)d_in[2];
    const float* Wout = (const float*)d_in[3];
    const float* bout = (const float*)d_in[4];
    float* out = (float*)d_out;

    __nv_bfloat16 *qkh, *qkl, *ah, *al, *wqh, *wql, *woh, *wol;
    cudaGetSymbolAddress((void**)&qkh, g_qkv_hi);
    cudaGetSymbolAddress((void**)&qkl, g_qkv_lo);
    cudaGetSymbolAddress((void**)&ah, g_a_hi);
    cudaGetSymbolAddress((void**)&al, g_a_lo);
    cudaGetSymbolAddress((void**)&wqh, g_wq_hi);
    cudaGetSymbolAddress((void**)&wql, g_wq_lo);
    cudaGetSymbolAddress((void**)&woh, g_wo_hi);
    cudaGetSymbolAddress((void**)&wol, g_wo_lo);

    cudaFuncSetAttribute(gemm_hmma<true>,  cudaFuncAttributeMaxDynamicSharedMemorySize, GEMM_SMEM);
    cudaFuncSetAttribute(gemm_hmma<false>, cudaFuncAttributeMaxDynamicSharedMemorySize, GEMM_SMEM);
    cudaFuncSetAttribute(attn_hmma, cudaFuncAttributeMaxDynamicSharedMemorySize, ATTN_SMEM);

    {
        int n4 = ROWS * D_MODEL / 4;
        split_kernel<<<(n4 + 255) / 256, 256>>>(x, ah, al, n4);
        transpose_split_kernel<<<dim3(QKV_N / 32, D_MODEL / 32), dim3(32, 8)>>>(
            Wqkv, wqh, wql, D_MODEL, QKV_N);
        transpose_split_kernel<<<dim3(D_MODEL / 32, D_MODEL / 32), dim3(32, 8)>>>(
            Wout, woh, wol, D_MODEL, D_MODEL);
    }

    gemm_hmma<true><<<dim3(QKV_N / 128, ROWS / 128), 256, GEMM_SMEM>>>(
        ah, al, wqh, wql, bqkv, nullptr, qkh, qkl, ROWS, QKV_N, D_MODEL);

    attn_hmma<<<dim3(SEQ / AT_BQ, BATCH * NHEADS), 256, ATTN_SMEM>>>(qkh, qkl, ah, al);

    gemm_hmma<false><<<dim3(D_MODEL / 128, ROWS / 128), 256, GEMM_SMEM>>>(
        ah, al, woh, wol, bout, out, nullptr, nullptr, ROWS, D_MODEL, D_MODEL);
}

// round 6
// speedup vs baseline: 1.3467x; 1.3467x over previous
#include <cuda_runtime.h>
#include <cuda_fp16.h>
#include <math.h>
#include <cstdint>

#define D_MODEL 2048
#define NHEADS  16
#define DK      128
#define BATCH   2
#define SEQ     2048
#define ROWS    (BATCH * SEQ)     // 4096
#define QKV_N   (3 * D_MODEL)     // 6144

// ---------------------------------------------------------------------------
// Scratch (device globals — no cudaMalloc allowed)
// ---------------------------------------------------------------------------
__device__ __half g_qkv_hi[ROWS * QKV_N];        // QKV hi (Q/K/V)
__device__ __half g_qkv_lo[ROWS * QKV_N];        // QKV lo (only Q cols used)
__device__ __half g_a_hi[ROWS * D_MODEL];        // x split hi, then attn-out hi
__device__ __half g_a_lo[ROWS * D_MODEL];
__device__ __half g_wq_h[QKV_N * D_MODEL];       // W_qkv^T fp16 (hi only)
__device__ __half g_wo_h[D_MODEL * D_MODEL];     // W_out^T fp16 (hi only)

// ---------------------------------------------------------------------------
// Base-target PTX helpers (virtual target is compute_103 — no tcgen05)
// ---------------------------------------------------------------------------
__device__ __forceinline__ uint32_t smem_u32(const void* p) {
    uint32_t a;
    asm("{ .reg .u64 t; cvta.to.shared.u64 t, %1; cvt.u32.u64 %0, t; }" : "=r"(a) : "l"(p));
    return a;
}
__device__ __forceinline__ void cp_async16(uint32_t saddr, const void* gaddr) {
    asm volatile("cp.async.cg.shared.global [%0], [%1], 16;" :: "r"(saddr), "l"(gaddr));
}
#define CP_COMMIT() asm volatile("cp.async.commit_group;" ::: "memory")
#define CP_WAIT(N)  asm volatile("cp.async.wait_group %0;" :: "n"(N) : "memory")

__device__ __forceinline__ void ldmx4(uint32_t* r, uint32_t addr) {
    asm volatile("ldmatrix.sync.aligned.m8n8.x4.shared.b16 {%0,%1,%2,%3}, [%4];"
                 : "=r"(r[0]), "=r"(r[1]), "=r"(r[2]), "=r"(r[3]) : "r"(addr));
}
__device__ __forceinline__ void ldmx4t(uint32_t* r, uint32_t addr) {
    asm volatile("ldmatrix.sync.aligned.m8n8.x4.trans.shared.b16 {%0,%1,%2,%3}, [%4];"
                 : "=r"(r[0]), "=r"(r[1]), "=r"(r[2]), "=r"(r[3]) : "r"(addr));
}
__device__ __forceinline__ void mma_fp16(float* d, const uint32_t* a, const uint32_t* b) {
    asm volatile(
        "mma.sync.aligned.m16n8k16.row.col.f32.f16.f16.f32 "
        "{%0,%1,%2,%3}, {%4,%5,%6,%7}, {%8,%9}, {%0,%1,%2,%3};"
        : "+f"(d[0]), "+f"(d[1]), "+f"(d[2]), "+f"(d[3])
        : "r"(a[0]), "r"(a[1]), "r"(a[2]), "r"(a[3]), "r"(b[0]), "r"(b[1]));
}

// pack 2 floats -> fp16x2 hi + fp16x2 residual-lo
__device__ __forceinline__ void split2h(float x, float y, uint32_t& h, uint32_t& l) {
    __half hx = __float2half(x), hy = __float2half(y);
    __half lx = __float2half(x - __half2float(hx));
    __half ly = __float2half(y - __half2float(hy));
    __half2 hh = __halves2half2(hx, hy);
    __half2 ll = __halves2half2(lx, ly);
    h = *(uint32_t*)&hh;
    l = *(uint32_t*)&ll;
}
__device__ __forceinline__ uint32_t pack2h(float x, float y) {
    __half2 hh = __halves2half2(__float2half(x), __float2half(y));
    return *(uint32_t*)&hh;
}

// GEMM smem tile: rows of 32 fp16 (64B = 4 x 16B chunks): chunk ^= (row>>1)&3
__device__ __forceinline__ uint32_t sw_off(int r, int c) {
    return (uint32_t)(r * 64 + ((c ^ ((r >> 1) & 3)) << 4));
}
// Attention smem tile: rows of 128 fp16 (256B = 16 x 16B chunks): chunk ^= row&7
__device__ __forceinline__ uint32_t asw(int row, int ch) {
    return (uint32_t)(row * 256 + ((ch ^ (row & 7)) << 4));
}

// ---------------------------------------------------------------------------
__global__ void split_kernel(const float* __restrict__ in,
                             __half* __restrict__ hi,
                             __half* __restrict__ lo, int n4)
{
    int i = blockIdx.x * blockDim.x + threadIdx.x;
    if (i >= n4) return;
    float4 v = ((const float4*)in)[i];
    uint32_t h0, l0, h1, l1;
    split2h(v.x, v.y, h0, l0);
    split2h(v.z, v.w, h1, l1);
    ((uint32_t*)hi)[2*i]   = h0;
    ((uint32_t*)hi)[2*i+1] = h1;
    ((uint32_t*)lo)[2*i]   = l0;
    ((uint32_t*)lo)[2*i+1] = l1;
}

// W[K,N] fp32 -> Wt[N,K] fp16 (hi only)
__global__ void transpose_half_kernel(const float* __restrict__ W,
                                      __half* __restrict__ Th,
                                      int K, int N)
{
    __shared__ float t[32][33];
    int k0 = blockIdx.y * 32, n0 = blockIdx.x * 32;
    #pragma unroll
    for (int i = threadIdx.y; i < 32; i += 8)
        t[i][threadIdx.x] = W[(size_t)(k0 + i) * N + n0 + threadIdx.x];
    __syncthreads();
    #pragma unroll
    for (int i = threadIdx.y; i < 32; i += 8)
        Th[(size_t)(n0 + i) * K + k0 + threadIdx.x] = __float2half(t[threadIdx.x][i]);
}

// ---------------------------------------------------------------------------
// HMMA GEMM: C[M,N] = A[M,K] @ Bt[N,K]^T + bias
// fp16: A = Ah + Al (2 products vs Bh). CTA 128x128, BK=32, 4-stage pipeline.
// ---------------------------------------------------------------------------
#define GM_BK    32
#define STAGES   4
#define TILE_B   8192                     // 128 rows x 64B
#define STAGE_B  (3 * TILE_B)             // Ah | Al | Bh
#define GEMM_SMEM (STAGES * STAGE_B)      // 96 KB
#define OFF_AH 0
#define OFF_AL TILE_B
#define OFF_BH (2 * TILE_B)

template<bool SPLIT>
__global__ __launch_bounds__(256) void gemm_hmma(
    const __half* __restrict__ Ah, const __half* __restrict__ Al,
    const __half* __restrict__ Bh,
    const float* __restrict__ bias, float* __restrict__ C,
    __half* __restrict__ Ch, __half* __restrict__ Cl,
    int M, int N, int K)
{
    extern __shared__ char smc[];
    const uint32_t sb = smem_u32(smc);
    const int tid  = threadIdx.x;
    const int warp = tid >> 5, lane = tid & 31;
    const int wm = warp >> 1, wn = warp & 1;
    const int bm = blockIdx.y, bn = blockIdx.x;
    const int NC = K / GM_BK;

    const __half* gAh = Ah + (size_t)bm * 128 * K;
    const __half* gAl = Al + (size_t)bm * 128 * K;
    const __half* gBh = Bh + (size_t)bn * 128 * K;

    const int r0 = tid >> 2, c0 = tid & 3;

    auto load_stage = [&](int chunk, int slot) {
        const int k0 = chunk * GM_BK;
        uint32_t base = sb + slot * STAGE_B;
        #pragma unroll
        for (int i = 0; i < 2; i++) {
            int r = r0 + i * 64;
            uint32_t so = sw_off(r, c0);
            size_t go = (size_t)r * K + k0 + c0 * 8;
            cp_async16(base + OFF_AH + so, gAh + go);
            cp_async16(base + OFF_AL + so, gAl + go);
            cp_async16(base + OFF_BH + so, gBh + go);
        }
        CP_COMMIT();
    };

    float acc[2][8][4];
    #pragma unroll
    for (int mt = 0; mt < 2; mt++)
        #pragma unroll
        for (int nt = 0; nt < 8; nt++)
            #pragma unroll
            for (int j = 0; j < 4; j++) acc[mt][nt][j] = 0.f;

    const int a_row = wm * 32 + (lane & 15);
    const int a_cb  = (lane >> 4) & 1;
    const int b_row = wn * 64 + (lane & 7) + ((lane & 16) ? 8 : 0);
    const int b_cb  = (lane >> 3) & 1;

    #pragma unroll
    for (int s = 0; s < STAGES - 1; s++) load_stage(s, s);

    for (int c = 0; c < NC; c++) {
        if (c + STAGES - 1 < NC) { CP_WAIT(STAGES - 2); }
        else                     { CP_WAIT(0); }
        __syncthreads();
        if (c + STAGES - 1 < NC) load_stage(c + STAGES - 1, (c + STAGES - 1) % STAGES);

        const uint32_t base = sb + (c % STAGES) * STAGE_B;

        #pragma unroll
        for (int ks = 0; ks < 2; ks++) {
            uint32_t ahf[2][4], alf[2][4];
            #pragma unroll
            for (int mt = 0; mt < 2; mt++) {
                uint32_t so = sw_off(a_row + mt * 16, 2 * ks + a_cb);
                ldmx4(ahf[mt], base + OFF_AH + so);
                ldmx4(alf[mt], base + OFF_AL + so);
            }
            uint32_t bhf[8][2];
            #pragma unroll
            for (int p = 0; p < 4; p++) {
                uint32_t so = sw_off(b_row + p * 16, 2 * ks + b_cb);
                uint32_t r[4];
                ldmx4(r, base + OFF_BH + so);
                bhf[2*p][0] = r[0]; bhf[2*p][1] = r[1];
                bhf[2*p+1][0] = r[2]; bhf[2*p+1][1] = r[3];
            }
            #pragma unroll
            for (int mt = 0; mt < 2; mt++)
                #pragma unroll
                for (int nt = 0; nt < 8; nt++) {
                    mma_fp16(acc[mt][nt], ahf[mt], bhf[nt]);
                    mma_fp16(acc[mt][nt], alf[mt], bhf[nt]);
                }
        }
    }

    const int erow = bm * 128 + wm * 32 + (lane >> 2);
    const int ecol = bn * 128 + wn * 64 + (lane & 3) * 2;
    #pragma unroll
    for (int mt = 0; mt < 2; mt++)
        #pragma unroll
        for (int nt = 0; nt < 8; nt++) {
            int col = ecol + nt * 8;
            float bx = bias[col], by = bias[col + 1];
            int ra = erow + mt * 16, rb = ra + 8;
            float v0 = acc[mt][nt][0] + bx, v1 = acc[mt][nt][1] + by;
            float v2 = acc[mt][nt][2] + bx, v3 = acc[mt][nt][3] + by;
            if (SPLIT) {
                // lo plane is only consumed for Q columns (head-local col < 128)
                bool isQ = (col % (3 * DK)) < DK;
                uint32_t hh, ll;
                split2h(v0, v1, hh, ll);
                *(uint32_t*)&Ch[(size_t)ra * N + col] = hh;
                if (isQ) *(uint32_t*)&Cl[(size_t)ra * N + col] = ll;
                split2h(v2, v3, hh, ll);
                *(uint32_t*)&Ch[(size_t)rb * N + col] = hh;
                if (isQ) *(uint32_t*)&Cl[(size_t)rb * N + col] = ll;
            } else {
                float2 o0 = {v0, v1}, o1 = {v2, v3};
                *(float2*)&C[(size_t)ra * N + col] = o0;
                *(float2*)&C[(size_t)rb * N + col] = o1;
            }
        }
}

// ---------------------------------------------------------------------------
// HMMA flash attention, fp16 2-product: Q = Qh+Ql (regs), K/V hi only,
// P split hi/lo in-register. 128 q-rows per CTA, 64-key tiles, double buffer.
// ---------------------------------------------------------------------------
#define AT_BQ 128
#define AT_BK 64
#define AT_NT (SEQ / AT_BK)          // 32
#define AQ_H 0
#define AQ_L 32768
#define AST(s) (65536 + (s) * 32768)
#define AK_H 0
#define AV_H 16384
#define ATTN_SMEM (65536 + 2 * 32768)   // 128 KB

__global__ __launch_bounds__(256, 1) void attn_hmma(
    const __half* __restrict__ qh_g, const __half* __restrict__ ql_g,
    __half* __restrict__ oh_g, __half* __restrict__ ol_g)
{
    extern __shared__ char smc[];
    const uint32_t sb = smem_u32(smc);
    const int tid = threadIdx.x, warp = tid >> 5, lane = tid & 31;
    const int qt = blockIdx.x, bh = blockIdx.y;
    const int b = bh >> 4, h = bh & 15;
    const size_t tok0  = (size_t)b * SEQ + qt * AT_BQ;
    const size_t ktok0 = (size_t)b * SEQ;
    const int colQ = h * 3 * DK, colK = colQ + DK, colV = colQ + 2 * DK;
    const float SCALE = 0.08838834764831845f;

    auto loadQ = [&]() {
        #pragma unroll
        for (int i = 0; i < 8; i++) {
            int idx = tid + i * 256;
            int r = idx >> 4, ch = idx & 15;
            uint32_t so = asw(r, ch);
            size_t g = (tok0 + r) * QKV_N + colQ + ch * 8;
            cp_async16(sb + AQ_H + so, qh_g + g);
            cp_async16(sb + AQ_L + so, ql_g + g);
        }
        CP_COMMIT();
    };
    auto loadK = [&](int kt, int s) {
        #pragma unroll
        for (int i = 0; i < 4; i++) {
            int idx = tid + i * 256;
            int r = idx >> 4, ch = idx & 15;
            size_t g = (ktok0 + kt * AT_BK + r) * QKV_N + colK + ch * 8;
            cp_async16(sb + AST(s) + AK_H + asw(r, ch), qh_g + g);
        }
        CP_COMMIT();
    };
    auto loadV = [&](int kt, int s) {
        #pragma unroll
        for (int i = 0; i < 4; i++) {
            int idx = tid + i * 256;
            int r = idx >> 4, ch = idx & 15;
            size_t g = (ktok0 + kt * AT_BK + r) * QKV_N + colV + ch * 8;
            cp_async16(sb + AST(s) + AV_H + asw(r, ch), qh_g + g);
        }
        CP_COMMIT();
    };

    const int aq_row = warp * 16 + (lane & 15);
    const int a_cb   = lane >> 4;
    const int bk_row = (lane & 7) + ((lane & 16) ? 8 : 0);
    const int bk_cb  = (lane >> 3) & 1;
    const int v_row  = (lane & 7) + (((lane >> 3) & 1) << 3);
    const int v_cb   = lane >> 4;

    float oacc[16][4];
    #pragma unroll
    for (int n = 0; n < 16; n++)
        #pragma unroll
        for (int j = 0; j < 4; j++) oacc[n][j] = 0.f;
    float m0 = -1e30f, m1 = -1e30f, l0 = 0.f, l1 = 0.f;

    // prologue: Q, K0, V0, K1
    loadQ();
    loadK(0, 0);
    loadV(0, 0);
    loadK(1, 1);

    // hoist Q fragments into registers
    CP_WAIT(3);
    __syncthreads();
    uint32_t qfh[8][4], qfl[8][4];
    #pragma unroll
    for (int ks = 0; ks < 8; ks++) {
        uint32_t qso = asw(aq_row, 2 * ks + a_cb);
        ldmx4(qfh[ks], sb + AQ_H + qso);
        ldmx4(qfl[ks], sb + AQ_L + qso);
    }

    for (int kt = 0; kt < AT_NT; kt++) {
        const int cur = kt & 1;

        CP_WAIT(2);              // K_kt complete
        __syncthreads();
        loadV((kt + 1) % AT_NT, cur ^ 1);   // wrap-around keeps counts exact

        const uint32_t kb = sb + AST(cur);

        // ---- S = Q K^T (2 products) ----
        float sacc[8][4];
        #pragma unroll
        for (int n = 0; n < 8; n++)
            #pragma unroll
            for (int j = 0; j < 4; j++) sacc[n][j] = 0.f;

        #pragma unroll
        for (int ks = 0; ks < 8; ks++) {
            #pragma unroll
            for (int p = 0; p < 4; p++) {
                uint32_t kh4[4];
                ldmx4(kh4, kb + AK_H + asw(p * 16 + bk_row, 2 * ks + bk_cb));
                mma_fp16(sacc[2*p],   qfh[ks], kh4);
                mma_fp16(sacc[2*p+1], qfh[ks], kh4 + 2);
                mma_fp16(sacc[2*p],   qfl[ks], kh4);
                mma_fp16(sacc[2*p+1], qfl[ks], kh4 + 2);
            }
        }

        // ---- online softmax ----
        float mx0 = -1e30f, mx1 = -1e30f;
        #pragma unroll
        for (int n = 0; n < 8; n++) {
            sacc[n][0] *= SCALE; sacc[n][1] *= SCALE;
            sacc[n][2] *= SCALE; sacc[n][3] *= SCALE;
            mx0 = fmaxf(mx0, fmaxf(sacc[n][0], sacc[n][1]));
            mx1 = fmaxf(mx1, fmaxf(sacc[n][2], sacc[n][3]));
        }
        mx0 = fmaxf(mx0, __shfl_xor_sync(0xffffffffu, mx0, 1));
        mx0 = fmaxf(mx0, __shfl_xor_sync(0xffffffffu, mx0, 2));
        mx1 = fmaxf(mx1, __shfl_xor_sync(0xffffffffu, mx1, 1));
        mx1 = fmaxf(mx1, __shfl_xor_sync(0xffffffffu, mx1, 2));
        const float mn0 = fmaxf(m0, mx0), mn1 = fmaxf(m1, mx1);

        float sum0 = 0.f, sum1 = 0.f;
        uint32_t ph[8][2], pl[8][2];
        #pragma unroll
        for (int n = 0; n < 8; n++) {
            float p00 = __expf(sacc[n][0] - mn0), p01 = __expf(sacc[n][1] - mn0);
            float p10 = __expf(sacc[n][2] - mn1), p11 = __expf(sacc[n][3] - mn1);
            sum0 += p00 + p01;
            sum1 += p10 + p11;
            split2h(p00, p01, ph[n][0], pl[n][0]);
            split2h(p10, p11, ph[n][1], pl[n][1]);
        }
        sum0 += __shfl_xor_sync(0xffffffffu, sum0, 1);
        sum0 += __shfl_xor_sync(0xffffffffu, sum0, 2);
        sum1 += __shfl_xor_sync(0xffffffffu, sum1, 1);
        sum1 += __shfl_xor_sync(0xffffffffu, sum1, 2);

        const float al0 = __expf(m0 - mn0), al1 = __expf(m1 - mn1);
        m0 = mn0; m1 = mn1;
        l0 = l0 * al0 + sum0;
        l1 = l1 * al1 + sum1;
        #pragma unroll
        for (int n = 0; n < 16; n++) {
            oacc[n][0] *= al0; oacc[n][1] *= al0;
            oacc[n][2] *= al1; oacc[n][3] *= al1;
        }

        CP_WAIT(2);              // V_kt complete
        __syncthreads();
        loadK((kt + 2) % AT_NT, cur);

        const uint32_t vb = sb + AST(cur);

        // ---- O += P V (2 products) ----
        #pragma unroll
        for (int kk = 0; kk < 4; kk++) {
            uint32_t pah[4] = {ph[2*kk][0], ph[2*kk][1], ph[2*kk+1][0], ph[2*kk+1][1]};
            uint32_t pal[4] = {pl[2*kk][0], pl[2*kk][1], pl[2*kk+1][0], pl[2*kk+1][1]};
            #pragma unroll
            for (int p = 0; p < 8; p++) {
                uint32_t vh4[4];
                ldmx4t(vh4, vb + AV_H + asw(kk * 16 + v_row, 2 * p + v_cb));
                mma_fp16(oacc[2*p],   pah, vh4);
                mma_fp16(oacc[2*p+1], pah, vh4 + 2);
                mma_fp16(oacc[2*p],   pal, vh4);
                mma_fp16(oacc[2*p+1], pal, vh4 + 2);
            }
        }
    }

    // ---- epilogue: normalize, split hi/lo, write ----
    const float inv0 = 1.f / l0, inv1 = 1.f / l1;
    const int rr = lane >> 2, c2 = (lane & 3) * 2;
    const size_t row0 = tok0 + warp * 16 + rr, row1 = row0 + 8;
    #pragma unroll
    for (int n = 0; n < 16; n++) {
        int col = h * DK + n * 8 + c2;
        uint32_t hh, ll;
        split2h(oacc[n][0] * inv0, oacc[n][1] * inv0, hh, ll);
        *(uint32_t*)&oh_g[row0 * D_MODEL + col] = hh;
        *(uint32_t*)&ol_g[row0 * D_MODEL + col] = ll;
        split2h(oacc[n][2] * inv1, oacc[n][3] * inv1, hh, ll);
        *(uint32_t*)&oh_g[row1 * D_MODEL + col] = hh;
        *(uint32_t*)&ol_g[row1 * D_MODEL + col] = ll;
    }
}

// ---------------------------------------------------------------------------
extern "C" void kernel_launch(void* const* d_in, const int* in_sizes, int n_in,
                              void* d_out, int out_size)
{
    const float* x    = (const float*)d_in[0];
    const float* Wqkv = (const float*)d_in[1];
    const float* bqkv = (const float*)d_in[2];
    const float* Wout = (const float*)d_in[3];
    const float* bout = (const float*)d_in[4];
    float* out = (float*)d_out;

    __half *qkh, *qkl, *ah, *al, *wqh, *woh;
    cudaGetSymbolAddress((void**)&qkh, g_qkv_hi);
    cudaGetSymbolAddress((void**)&qkl, g_qkv_lo);
    cudaGetSymbolAddress((void**)&ah, g_a_hi);
    cudaGetSymbolAddress((void**)&al, g_a_lo);
    cudaGetSymbolAddress((void**)&wqh, g_wq_h);
    cudaGetSymbolAddress((void**)&woh, g_wo_h);

    cudaFuncSetAttribute(gemm_hmma<true>,  cudaFuncAttributeMaxDynamicSharedMemorySize, GEMM_SMEM);
    cudaFuncSetAttribute(gemm_hmma<false>, cudaFuncAttributeMaxDynamicSharedMemorySize, GEMM_SMEM);
    cudaFuncSetAttribute(attn_hmma, cudaFuncAttributeMaxDynamicSharedMemorySize, ATTN_SMEM);

    {
        int n4 = ROWS * D_MODEL / 4;
        split_kernel<<<(n4 + 255) / 256, 256>>>(x, ah, al, n4);
        transpose_half_kernel<<<dim3(QKV_N / 32, D_MODEL / 32), dim3(32, 8)>>>(
            Wqkv, wqh, D_MODEL, QKV_N);
        transpose_half_kernel<<<dim3(D_MODEL / 32, D_MODEL / 32), dim3(32, 8)>>>(
            Wout, woh, D_MODEL, D_MODEL);
    }

    // 1) QKV projection: epilogue writes fp16 hi (all cols) + lo (Q cols)
    gemm_hmma<true><<<dim3(QKV_N / 128, ROWS / 128), 256, GEMM_SMEM>>>(
        ah, al, wqh, bqkv, nullptr, qkh, qkl, ROWS, QKV_N, D_MODEL);

    // 2) attention
    attn_hmma<<<dim3(SEQ / AT_BQ, BATCH * NHEADS), 256, ATTN_SMEM>>>(qkh, qkl, ah, al);

    // 3) out-projection, fp32 output
    gemm_hmma<false><<<dim3(D_MODEL / 128, ROWS / 128), 256, GEMM_SMEM>>>(
        ah, al, woh, bout, out, nullptr, nullptr, ROWS, D_MODEL, D_MODEL);
}

// round 7
// speedup vs baseline: 1.4698x; 1.0914x over previous
#include <cuda_runtime.h>
#include <cuda_fp16.h>
#include <math.h>
#include <cstdint>

#define D_MODEL 2048
#define NHEADS  16
#define DK      128
#define BATCH   2
#define SEQ     2048
#define ROWS    (BATCH * SEQ)     // 4096
#define QKV_N   (3 * D_MODEL)     // 6144

// ---------------------------------------------------------------------------
// Scratch (device globals — no cudaMalloc allowed)
// ---------------------------------------------------------------------------
__device__ __half g_qkv_hi[ROWS * QKV_N];        // QKV hi (Q/K/V)
__device__ __half g_qkv_lo[ROWS * QKV_N];        // QKV lo (only Q cols used)
__device__ __half g_a_hi[ROWS * D_MODEL];        // x split hi, then attn-out hi
__device__ __half g_a_lo[ROWS * D_MODEL];
__device__ __half g_wq_h[QKV_N * D_MODEL];       // W_qkv^T fp16 (hi only)
__device__ __half g_wo_h[D_MODEL * D_MODEL];     // W_out^T fp16 (hi only)

// ---------------------------------------------------------------------------
// Base-target PTX helpers (virtual target is compute_103 — no tcgen05)
// ---------------------------------------------------------------------------
__device__ __forceinline__ uint32_t smem_u32(const void* p) {
    uint32_t a;
    asm("{ .reg .u64 t; cvta.to.shared.u64 t, %1; cvt.u32.u64 %0, t; }" : "=r"(a) : "l"(p));
    return a;
}
__device__ __forceinline__ void cp_async16(uint32_t saddr, const void* gaddr) {
    asm volatile("cp.async.cg.shared.global [%0], [%1], 16;" :: "r"(saddr), "l"(gaddr));
}
#define CP_COMMIT() asm volatile("cp.async.commit_group;" ::: "memory")
#define CP_WAIT(N)  asm volatile("cp.async.wait_group %0;" :: "n"(N) : "memory")

__device__ __forceinline__ void ldmx4(uint32_t* r, uint32_t addr) {
    asm volatile("ldmatrix.sync.aligned.m8n8.x4.shared.b16 {%0,%1,%2,%3}, [%4];"
                 : "=r"(r[0]), "=r"(r[1]), "=r"(r[2]), "=r"(r[3]) : "r"(addr));
}
__device__ __forceinline__ void ldmx4t(uint32_t* r, uint32_t addr) {
    asm volatile("ldmatrix.sync.aligned.m8n8.x4.trans.shared.b16 {%0,%1,%2,%3}, [%4];"
                 : "=r"(r[0]), "=r"(r[1]), "=r"(r[2]), "=r"(r[3]) : "r"(addr));
}
__device__ __forceinline__ void mma_fp16(float* d, const uint32_t* a, const uint32_t* b) {
    asm volatile(
        "mma.sync.aligned.m16n8k16.row.col.f32.f16.f16.f32 "
        "{%0,%1,%2,%3}, {%4,%5,%6,%7}, {%8,%9}, {%0,%1,%2,%3};"
        : "+f"(d[0]), "+f"(d[1]), "+f"(d[2]), "+f"(d[3])
        : "r"(a[0]), "r"(a[1]), "r"(a[2]), "r"(a[3]), "r"(b[0]), "r"(b[1]));
}

// pack 2 floats -> fp16x2 hi + fp16x2 residual-lo
__device__ __forceinline__ void split2h(float x, float y, uint32_t& h, uint32_t& l) {
    __half hx = __float2half(x), hy = __float2half(y);
    __half lx = __float2half(x - __half2float(hx));
    __half ly = __float2half(y - __half2float(hy));
    __half2 hh = __halves2half2(hx, hy);
    __half2 ll = __halves2half2(lx, ly);
    h = *(uint32_t*)&hh;
    l = *(uint32_t*)&ll;
}

// GEMM smem tile: rows of 32 fp16 (64B = 4 x 16B chunks): chunk ^= (row>>1)&3
__device__ __forceinline__ uint32_t sw_off(int r, int c) {
    return (uint32_t)(r * 64 + ((c ^ ((r >> 1) & 3)) << 4));
}
// Attention smem tile: rows of 128 fp16 (256B = 16 x 16B chunks): chunk ^= row&7
__device__ __forceinline__ uint32_t asw(int row, int ch) {
    return (uint32_t)(row * 256 + ((ch ^ (row & 7)) << 4));
}

// ---------------------------------------------------------------------------
__global__ void split_kernel(const float* __restrict__ in,
                             __half* __restrict__ hi,
                             __half* __restrict__ lo, int n4)
{
    int i = blockIdx.x * blockDim.x + threadIdx.x;
    if (i >= n4) return;
    float4 v = ((const float4*)in)[i];
    uint32_t h0, l0, h1, l1;
    split2h(v.x, v.y, h0, l0);
    split2h(v.z, v.w, h1, l1);
    ((uint32_t*)hi)[2*i]   = h0;
    ((uint32_t*)hi)[2*i+1] = h1;
    ((uint32_t*)lo)[2*i]   = l0;
    ((uint32_t*)lo)[2*i+1] = l1;
}

// W[K,N] fp32 -> Wt[N,K] fp16 (hi only)
__global__ void transpose_half_kernel(const float* __restrict__ W,
                                      __half* __restrict__ Th,
                                      int K, int N)
{
    __shared__ float t[32][33];
    int k0 = blockIdx.y * 32, n0 = blockIdx.x * 32;
    #pragma unroll
    for (int i = threadIdx.y; i < 32; i += 8)
        t[i][threadIdx.x] = W[(size_t)(k0 + i) * N + n0 + threadIdx.x];
    __syncthreads();
    #pragma unroll
    for (int i = threadIdx.y; i < 32; i += 8)
        Th[(size_t)(n0 + i) * K + k0 + threadIdx.x] = __float2half(t[threadIdx.x][i]);
}

// ---------------------------------------------------------------------------
// HMMA GEMM: C[M,N] = A[M,K] @ Bt[N,K]^T + bias
// fp16: A = Ah + Al (2 products vs Bh). CTA 128x128, BK=32, 4-stage pipeline.
// __launch_bounds__(256,2): force 128-reg cap so 2 CTAs/SM fit the regfile.
// ---------------------------------------------------------------------------
#define GM_BK    32
#define STAGES   4
#define TILE_B   8192                     // 128 rows x 64B
#define STAGE_B  (3 * TILE_B)             // Ah | Al | Bh
#define GEMM_SMEM (STAGES * STAGE_B)      // 96 KB
#define OFF_AH 0
#define OFF_AL TILE_B
#define OFF_BH (2 * TILE_B)

template<bool SPLIT>
__global__ __launch_bounds__(256, 2) void gemm_hmma(
    const __half* __restrict__ Ah, const __half* __restrict__ Al,
    const __half* __restrict__ Bh,
    const float* __restrict__ bias, float* __restrict__ C,
    __half* __restrict__ Ch, __half* __restrict__ Cl,
    int M, int N, int K)
{
    extern __shared__ char smc[];
    const uint32_t sb = smem_u32(smc);
    const int tid  = threadIdx.x;
    const int warp = tid >> 5, lane = tid & 31;
    const int wm = warp >> 1, wn = warp & 1;
    const int bm = blockIdx.y, bn = blockIdx.x;
    const int NC = K / GM_BK;

    const __half* gAh = Ah + (size_t)bm * 128 * K;
    const __half* gAl = Al + (size_t)bm * 128 * K;
    const __half* gBh = Bh + (size_t)bn * 128 * K;

    const int r0 = tid >> 2, c0 = tid & 3;

    auto load_stage = [&](int chunk, int slot) {
        const int k0 = chunk * GM_BK;
        uint32_t base = sb + slot * STAGE_B;
        #pragma unroll
        for (int i = 0; i < 2; i++) {
            int r = r0 + i * 64;
            uint32_t so = sw_off(r, c0);
            size_t go = (size_t)r * K + k0 + c0 * 8;
            cp_async16(base + OFF_AH + so, gAh + go);
            cp_async16(base + OFF_AL + so, gAl + go);
            cp_async16(base + OFF_BH + so, gBh + go);
        }
        CP_COMMIT();
    };

    float acc[2][8][4];
    #pragma unroll
    for (int mt = 0; mt < 2; mt++)
        #pragma unroll
        for (int nt = 0; nt < 8; nt++)
            #pragma unroll
            for (int j = 0; j < 4; j++) acc[mt][nt][j] = 0.f;

    const int a_row = wm * 32 + (lane & 15);
    const int a_cb  = (lane >> 4) & 1;
    const int b_row = wn * 64 + (lane & 7) + ((lane & 16) ? 8 : 0);
    const int b_cb  = (lane >> 3) & 1;

    #pragma unroll
    for (int s = 0; s < STAGES - 1; s++) load_stage(s, s);

    for (int c = 0; c < NC; c++) {
        if (c + STAGES - 1 < NC) { CP_WAIT(STAGES - 2); }
        else                     { CP_WAIT(0); }
        __syncthreads();
        if (c + STAGES - 1 < NC) load_stage(c + STAGES - 1, (c + STAGES - 1) % STAGES);

        const uint32_t base = sb + (c % STAGES) * STAGE_B;

        #pragma unroll
        for (int ks = 0; ks < 2; ks++) {
            uint32_t ahf[2][4], alf[2][4];
            #pragma unroll
            for (int mt = 0; mt < 2; mt++) {
                uint32_t so = sw_off(a_row + mt * 16, 2 * ks + a_cb);
                ldmx4(ahf[mt], base + OFF_AH + so);
                ldmx4(alf[mt], base + OFF_AL + so);
            }
            uint32_t bhf[8][2];
            #pragma unroll
            for (int p = 0; p < 4; p++) {
                uint32_t so = sw_off(b_row + p * 16, 2 * ks + b_cb);
                uint32_t r[4];
                ldmx4(r, base + OFF_BH + so);
                bhf[2*p][0] = r[0]; bhf[2*p][1] = r[1];
                bhf[2*p+1][0] = r[2]; bhf[2*p+1][1] = r[3];
            }
            #pragma unroll
            for (int mt = 0; mt < 2; mt++)
                #pragma unroll
                for (int nt = 0; nt < 8; nt++) {
                    mma_fp16(acc[mt][nt], ahf[mt], bhf[nt]);
                    mma_fp16(acc[mt][nt], alf[mt], bhf[nt]);
                }
        }
    }

    const int erow = bm * 128 + wm * 32 + (lane >> 2);
    const int ecol = bn * 128 + wn * 64 + (lane & 3) * 2;
    #pragma unroll
    for (int mt = 0; mt < 2; mt++)
        #pragma unroll
        for (int nt = 0; nt < 8; nt++) {
            int col = ecol + nt * 8;
            float bx = bias[col], by = bias[col + 1];
            int ra = erow + mt * 16, rb = ra + 8;
            float v0 = acc[mt][nt][0] + bx, v1 = acc[mt][nt][1] + by;
            float v2 = acc[mt][nt][2] + bx, v3 = acc[mt][nt][3] + by;
            if (SPLIT) {
                // lo plane is only consumed for Q columns (head-local col < 128)
                bool isQ = (col % (3 * DK)) < DK;
                uint32_t hh, ll;
                split2h(v0, v1, hh, ll);
                *(uint32_t*)&Ch[(size_t)ra * N + col] = hh;
                if (isQ) *(uint32_t*)&Cl[(size_t)ra * N + col] = ll;
                split2h(v2, v3, hh, ll);
                *(uint32_t*)&Ch[(size_t)rb * N + col] = hh;
                if (isQ) *(uint32_t*)&Cl[(size_t)rb * N + col] = ll;
            } else {
                float2 o0 = {v0, v1}, o1 = {v2, v3};
                *(float2*)&C[(size_t)ra * N + col] = o0;
                *(float2*)&C[(size_t)rb * N + col] = o1;
            }
        }
}

// ---------------------------------------------------------------------------
// HMMA flash attention, fp16 2-product: Q = Qh+Ql (regs), K/V hi only,
// P split hi/lo in-register. 128 q-rows per CTA, 64-key tiles, double buffer.
// ---------------------------------------------------------------------------
#define AT_BQ 128
#define AT_BK 64
#define AT_NT (SEQ / AT_BK)          // 32
#define AQ_H 0
#define AQ_L 32768
#define AST(s) (65536 + (s) * 32768)
#define AK_H 0
#define AV_H 16384
#define ATTN_SMEM (65536 + 2 * 32768)   // 128 KB

__global__ __launch_bounds__(256, 1) void attn_hmma(
    const __half* __restrict__ qh_g, const __half* __restrict__ ql_g,
    __half* __restrict__ oh_g, __half* __restrict__ ol_g)
{
    extern __shared__ char smc[];
    const uint32_t sb = smem_u32(smc);
    const int tid = threadIdx.x, warp = tid >> 5, lane = tid & 31;
    const int qt = blockIdx.x, bh = blockIdx.y;
    const int b = bh >> 4, h = bh & 15;
    const size_t tok0  = (size_t)b * SEQ + qt * AT_BQ;
    const size_t ktok0 = (size_t)b * SEQ;
    const int colQ = h * 3 * DK, colK = colQ + DK, colV = colQ + 2 * DK;
    const float SCALE = 0.08838834764831845f;

    auto loadQ = [&]() {
        #pragma unroll
        for (int i = 0; i < 8; i++) {
            int idx = tid + i * 256;
            int r = idx >> 4, ch = idx & 15;
            uint32_t so = asw(r, ch);
            size_t g = (tok0 + r) * QKV_N + colQ + ch * 8;
            cp_async16(sb + AQ_H + so, qh_g + g);
            cp_async16(sb + AQ_L + so, ql_g + g);
        }
        CP_COMMIT();
    };
    auto loadK = [&](int kt, int s) {
        #pragma unroll
        for (int i = 0; i < 4; i++) {
            int idx = tid + i * 256;
            int r = idx >> 4, ch = idx & 15;
            size_t g = (ktok0 + kt * AT_BK + r) * QKV_N + colK + ch * 8;
            cp_async16(sb + AST(s) + AK_H + asw(r, ch), qh_g + g);
        }
        CP_COMMIT();
    };
    auto loadV = [&](int kt, int s) {
        #pragma unroll
        for (int i = 0; i < 4; i++) {
            int idx = tid + i * 256;
            int r = idx >> 4, ch = idx & 15;
            size_t g = (ktok0 + kt * AT_BK + r) * QKV_N + colV + ch * 8;
            cp_async16(sb + AST(s) + AV_H + asw(r, ch), qh_g + g);
        }
        CP_COMMIT();
    };

    const int aq_row = warp * 16 + (lane & 15);
    const int a_cb   = lane >> 4;
    const int bk_row = (lane & 7) + ((lane & 16) ? 8 : 0);
    const int bk_cb  = (lane >> 3) & 1;
    const int v_row  = (lane & 7) + (((lane >> 3) & 1) << 3);
    const int v_cb   = lane >> 4;

    float oacc[16][4];
    #pragma unroll
    for (int n = 0; n < 16; n++)
        #pragma unroll
        for (int j = 0; j < 4; j++) oacc[n][j] = 0.f;
    float m0 = -1e30f, m1 = -1e30f, l0 = 0.f, l1 = 0.f;

    // prologue: Q, K0, V0, K1
    loadQ();
    loadK(0, 0);
    loadV(0, 0);
    loadK(1, 1);

    // hoist Q fragments into registers
    CP_WAIT(3);
    __syncthreads();
    uint32_t qfh[8][4], qfl[8][4];
    #pragma unroll
    for (int ks = 0; ks < 8; ks++) {
        uint32_t qso = asw(aq_row, 2 * ks + a_cb);
        ldmx4(qfh[ks], sb + AQ_H + qso);
        ldmx4(qfl[ks], sb + AQ_L + qso);
    }

    for (int kt = 0; kt < AT_NT; kt++) {
        const int cur = kt & 1;

        CP_WAIT(2);              // K_kt complete
        __syncthreads();
        loadV((kt + 1) % AT_NT, cur ^ 1);   // wrap-around keeps counts exact

        const uint32_t kb = sb + AST(cur);

        // ---- S = Q K^T (2 products) ----
        float sacc[8][4];
        #pragma unroll
        for (int n = 0; n < 8; n++)
            #pragma unroll
            for (int j = 0; j < 4; j++) sacc[n][j] = 0.f;

        #pragma unroll
        for (int ks = 0; ks < 8; ks++) {
            #pragma unroll
            for (int p = 0; p < 4; p++) {
                uint32_t kh4[4];
                ldmx4(kh4, kb + AK_H + asw(p * 16 + bk_row, 2 * ks + bk_cb));
                mma_fp16(sacc[2*p],   qfh[ks], kh4);
                mma_fp16(sacc[2*p+1], qfh[ks], kh4 + 2);
                mma_fp16(sacc[2*p],   qfl[ks], kh4);
                mma_fp16(sacc[2*p+1], qfl[ks], kh4 + 2);
            }
        }

        // ---- online softmax ----
        float mx0 = -1e30f, mx1 = -1e30f;
        #pragma unroll
        for (int n = 0; n < 8; n++) {
            sacc[n][0] *= SCALE; sacc[n][1] *= SCALE;
            sacc[n][2] *= SCALE; sacc[n][3] *= SCALE;
            mx0 = fmaxf(mx0, fmaxf(sacc[n][0], sacc[n][1]));
            mx1 = fmaxf(mx1, fmaxf(sacc[n][2], sacc[n][3]));
        }
        mx0 = fmaxf(mx0, __shfl_xor_sync(0xffffffffu, mx0, 1));
        mx0 = fmaxf(mx0, __shfl_xor_sync(0xffffffffu, mx0, 2));
        mx1 = fmaxf(mx1, __shfl_xor_sync(0xffffffffu, mx1, 1));
        mx1 = fmaxf(mx1, __shfl_xor_sync(0xffffffffu, mx1, 2));
        const float mn0 = fmaxf(m0, mx0), mn1 = fmaxf(m1, mx1);

        float sum0 = 0.f, sum1 = 0.f;
        uint32_t ph[8][2], pl[8][2];
        #pragma unroll
        for (int n = 0; n < 8; n++) {
            float p00 = __expf(sacc[n][0] - mn0), p01 = __expf(sacc[n][1] - mn0);
            float p10 = __expf(sacc[n][2] - mn1), p11 = __expf(sacc[n][3] - mn1);
            sum0 += p00 + p01;
            sum1 += p10 + p11;
            split2h(p00, p01, ph[n][0], pl[n][0]);
            split2h(p10, p11, ph[n][1], pl[n][1]);
        }
        sum0 += __shfl_xor_sync(0xffffffffu, sum0, 1);
        sum0 += __shfl_xor_sync(0xffffffffu, sum0, 2);
        sum1 += __shfl_xor_sync(0xffffffffu, sum1, 1);
        sum1 += __shfl_xor_sync(0xffffffffu, sum1, 2);

        const float al0 = __expf(m0 - mn0), al1 = __expf(m1 - mn1);
        m0 = mn0; m1 = mn1;
        l0 = l0 * al0 + sum0;
        l1 = l1 * al1 + sum1;
        #pragma unroll
        for (int n = 0; n < 16; n++) {
            oacc[n][0] *= al0; oacc[n][1] *= al0;
            oacc[n][2] *= al1; oacc[n][3] *= al1;
        }

        CP_WAIT(2);              // V_kt complete
        __syncthreads();
        loadK((kt + 2) % AT_NT, cur);

        const uint32_t vb = sb + AST(cur);

        // ---- O += P V (2 products) ----
        #pragma unroll
        for (int kk = 0; kk < 4; kk++) {
            uint32_t pah[4] = {ph[2*kk][0], ph[2*kk][1], ph[2*kk+1][0], ph[2*kk+1][1]};
            uint32_t pal[4] = {pl[2*kk][0], pl[2*kk][1], pl[2*kk+1][0], pl[2*kk+1][1]};
            #pragma unroll
            for (int p = 0; p < 8; p++) {
                uint32_t vh4[4];
                ldmx4t(vh4, vb + AV_H + asw(kk * 16 + v_row, 2 * p + v_cb));
                mma_fp16(oacc[2*p],   pah, vh4);
                mma_fp16(oacc[2*p+1], pah, vh4 + 2);
                mma_fp16(oacc[2*p],   pal, vh4);
                mma_fp16(oacc[2*p+1], pal, vh4 + 2);
            }
        }
    }

    // ---- epilogue: normalize, split hi/lo, write ----
    const float inv0 = 1.f / l0, inv1 = 1.f / l1;
    const int rr = lane >> 2, c2 = (lane & 3) * 2;
    const size_t row0 = tok0 + warp * 16 + rr, row1 = row0 + 8;
    #pragma unroll
    for (int n = 0; n < 16; n++) {
        int col = h * DK + n * 8 + c2;
        uint32_t hh, ll;
        split2h(oacc[n][0] * inv0, oacc[n][1] * inv0, hh, ll);
        *(uint32_t*)&oh_g[row0 * D_MODEL + col] = hh;
        *(uint32_t*)&ol_g[row0 * D_MODEL + col] = ll;
        split2h(oacc[n][2] * inv1, oacc[n][3] * inv1, hh, ll);
        *(uint32_t*)&oh_g[row1 * D_MODEL + col] = hh;
        *(uint32_t*)&ol_g[row1 * D_MODEL + col] = ll;
    }
}

// ---------------------------------------------------------------------------
extern "C" void kernel_launch(void* const* d_in, const int* in_sizes, int n_in,
                              void* d_out, int out_size)
{
    const float* x    = (const float*)d_in[0];
    const float* Wqkv = (const float*)d_in[1];
    const float* bqkv = (const float*)d_in[2];
    const float* Wout = (const float*)d_in[3];
    const float* bout = (const float*)d_in[4];
    float* out = (float*)d_out;

    __half *qkh, *qkl, *ah, *al, *wqh, *woh;
    cudaGetSymbolAddress((void**)&qkh, g_qkv_hi);
    cudaGetSymbolAddress((void**)&qkl, g_qkv_lo);
    cudaGetSymbolAddress((void**)&ah, g_a_hi);
    cudaGetSymbolAddress((void**)&al, g_a_lo);
    cudaGetSymbolAddress((void**)&wqh, g_wq_h);
    cudaGetSymbolAddress((void**)&woh, g_wo_h);

    cudaFuncSetAttribute(gemm_hmma<true>,  cudaFuncAttributeMaxDynamicSharedMemorySize, GEMM_SMEM);
    cudaFuncSetAttribute(gemm_hmma<false>, cudaFuncAttributeMaxDynamicSharedMemorySize, GEMM_SMEM);
    cudaFuncSetAttribute(attn_hmma, cudaFuncAttributeMaxDynamicSharedMemorySize, ATTN_SMEM);

    {
        int n4 = ROWS * D_MODEL / 4;
        split_kernel<<<(n4 + 255) / 256, 256>>>(x, ah, al, n4);
        transpose_half_kernel<<<dim3(QKV_N / 32, D_MODEL / 32), dim3(32, 8)>>>(
            Wqkv, wqh, D_MODEL, QKV_N);
        transpose_half_kernel<<<dim3(D_MODEL / 32, D_MODEL / 32), dim3(32, 8)>>>(
            Wout, woh, D_MODEL, D_MODEL);
    }

    // 1) QKV projection: epilogue writes fp16 hi (all cols) + lo (Q cols)
    gemm_hmma<true><<<dim3(QKV_N / 128, ROWS / 128), 256, GEMM_SMEM>>>(
        ah, al, wqh, bqkv, nullptr, qkh, qkl, ROWS, QKV_N, D_MODEL);

    // 2) attention
    attn_hmma<<<dim3(SEQ / AT_BQ, BATCH * NHEADS), 256, ATTN_SMEM>>>(qkh, qkl, ah, al);

    // 3) out-projection, fp32 output
    gemm_hmma<false><<<dim3(D_MODEL / 128, ROWS / 128), 256, GEMM_SMEM>>>(
        ah, al, woh, bout, out, nullptr, nullptr, ROWS, D_MODEL, D_MODEL);
}

// round 8
// speedup vs baseline: 1.4753x; 1.0038x over previous
#include <cuda_runtime.h>
#include <cuda_fp16.h>
#include <math.h>
#include <cstdint>

#define D_MODEL 2048
#define NHEADS  16
#define DK      128
#define BATCH   2
#define SEQ     2048
#define ROWS    (BATCH * SEQ)     // 4096
#define QKV_N   (3 * D_MODEL)     // 6144

// ---------------------------------------------------------------------------
// Scratch (device globals — no cudaMalloc allowed)
// ---------------------------------------------------------------------------
__device__ __half g_qkv_hi[ROWS * QKV_N];        // QKV hi (Q/K/V)
__device__ __half g_qkv_lo[ROWS * QKV_N];        // QKV lo (only Q cols used)
__device__ __half g_a_hi[ROWS * D_MODEL];        // x split hi, then attn-out hi
__device__ __half g_a_lo[ROWS * D_MODEL];
__device__ __half g_wq_h[QKV_N * D_MODEL];       // W_qkv^T fp16 (hi only)
__device__ __half g_wo_h[D_MODEL * D_MODEL];     // W_out^T fp16 (hi only)

// ---------------------------------------------------------------------------
// Base-target PTX helpers (virtual target is compute_103 — no tcgen05)
// ---------------------------------------------------------------------------
__device__ __forceinline__ uint32_t smem_u32(const void* p) {
    uint32_t a;
    asm("{ .reg .u64 t; cvta.to.shared.u64 t, %1; cvt.u32.u64 %0, t; }" : "=r"(a) : "l"(p));
    return a;
}
__device__ __forceinline__ void cp_async16(uint32_t saddr, const void* gaddr) {
    asm volatile("cp.async.cg.shared.global [%0], [%1], 16;" :: "r"(saddr), "l"(gaddr));
}
#define CP_COMMIT() asm volatile("cp.async.commit_group;" ::: "memory")
#define CP_WAIT(N)  asm volatile("cp.async.wait_group %0;" :: "n"(N) : "memory")

__device__ __forceinline__ void ldmx4(uint32_t* r, uint32_t addr) {
    asm volatile("ldmatrix.sync.aligned.m8n8.x4.shared.b16 {%0,%1,%2,%3}, [%4];"
                 : "=r"(r[0]), "=r"(r[1]), "=r"(r[2]), "=r"(r[3]) : "r"(addr));
}
__device__ __forceinline__ void ldmx4t(uint32_t* r, uint32_t addr) {
    asm volatile("ldmatrix.sync.aligned.m8n8.x4.trans.shared.b16 {%0,%1,%2,%3}, [%4];"
                 : "=r"(r[0]), "=r"(r[1]), "=r"(r[2]), "=r"(r[3]) : "r"(addr));
}
__device__ __forceinline__ void mma_fp16(float* d, const uint32_t* a, const uint32_t* b) {
    asm volatile(
        "mma.sync.aligned.m16n8k16.row.col.f32.f16.f16.f32 "
        "{%0,%1,%2,%3}, {%4,%5,%6,%7}, {%8,%9}, {%0,%1,%2,%3};"
        : "+f"(d[0]), "+f"(d[1]), "+f"(d[2]), "+f"(d[3])
        : "r"(a[0]), "r"(a[1]), "r"(a[2]), "r"(a[3]), "r"(b[0]), "r"(b[1]));
}

// pack 2 floats -> fp16x2 hi + fp16x2 residual-lo
__device__ __forceinline__ void split2h(float x, float y, uint32_t& h, uint32_t& l) {
    __half hx = __float2half(x), hy = __float2half(y);
    __half lx = __float2half(x - __half2float(hx));
    __half ly = __float2half(y - __half2float(hy));
    __half2 hh = __halves2half2(hx, hy);
    __half2 ll = __halves2half2(lx, ly);
    h = *(uint32_t*)&hh;
    l = *(uint32_t*)&ll;
}

// GEMM smem tile: rows of 32 fp16 (64B = 4 x 16B chunks): chunk ^= (row>>1)&3
__device__ __forceinline__ uint32_t sw_off(int r, int c) {
    return (uint32_t)(r * 64 + ((c ^ ((r >> 1) & 3)) << 4));
}
// Attention smem tile: rows of 128 fp16 (256B = 16 x 16B chunks): chunk ^= row&7
__device__ __forceinline__ uint32_t asw(int row, int ch) {
    return (uint32_t)(row * 256 + ((ch ^ (row & 7)) << 4));
}

// ---------------------------------------------------------------------------
__global__ void split_kernel(const float* __restrict__ in,
                             __half* __restrict__ hi,
                             __half* __restrict__ lo, int n4)
{
    int i = blockIdx.x * blockDim.x + threadIdx.x;
    if (i >= n4) return;
    float4 v = ((const float4*)in)[i];
    uint32_t h0, l0, h1, l1;
    split2h(v.x, v.y, h0, l0);
    split2h(v.z, v.w, h1, l1);
    ((uint32_t*)hi)[2*i]   = h0;
    ((uint32_t*)hi)[2*i+1] = h1;
    ((uint32_t*)lo)[2*i]   = l0;
    ((uint32_t*)lo)[2*i+1] = l1;
}

// W[K,N] fp32 -> Wt[N,K] fp16 (hi only)
__global__ void transpose_half_kernel(const float* __restrict__ W,
                                      __half* __restrict__ Th,
                                      int K, int N)
{
    __shared__ float t[32][33];
    int k0 = blockIdx.y * 32, n0 = blockIdx.x * 32;
    #pragma unroll
    for (int i = threadIdx.y; i < 32; i += 8)
        t[i][threadIdx.x] = W[(size_t)(k0 + i) * N + n0 + threadIdx.x];
    __syncthreads();
    #pragma unroll
    for (int i = threadIdx.y; i < 32; i += 8)
        Th[(size_t)(n0 + i) * K + k0 + threadIdx.x] = __float2half(t[threadIdx.x][i]);
}

// ---------------------------------------------------------------------------
// HMMA GEMM: C[M,N] = A[M,K] @ Bt[N,K]^T + bias
// fp16: A = Ah + Al. QKV_MODE: CTAs on K/V column blocks (bn%3 != 0) use a
// single Ah product — their outputs are consumed as fp16-hi only, so the
// dropped Al term (~1.6e-4 rel) is below their store rounding anyway.
// ---------------------------------------------------------------------------
#define GM_BK    32
#define STAGES   4
#define TILE_B   8192                     // 128 rows x 64B
#define STAGE_B  (3 * TILE_B)             // Ah | Al | Bh
#define GEMM_SMEM (STAGES * STAGE_B)      // 96 KB
#define OFF_AH 0
#define OFF_AL TILE_B
#define OFF_BH (2 * TILE_B)

template<bool SPLIT, bool QKV_MODE>
__global__ __launch_bounds__(256, 2) void gemm_hmma(
    const __half* __restrict__ Ah, const __half* __restrict__ Al,
    const __half* __restrict__ Bh,
    const float* __restrict__ bias, float* __restrict__ C,
    __half* __restrict__ Ch, __half* __restrict__ Cl,
    int M, int N, int K)
{
    extern __shared__ char smc[];
    const uint32_t sb = smem_u32(smc);
    const int tid  = threadIdx.x;
    const int warp = tid >> 5, lane = tid & 31;
    const int wm = warp >> 1, wn = warp & 1;
    const int bm = blockIdx.y, bn = blockIdx.x;
    const int NC = K / GM_BK;
    // Q column-block CTAs need the Al product; K/V blocks don't.
    const bool twoProd = !QKV_MODE || (bn % 3 == 0);

    const __half* gAh = Ah + (size_t)bm * 128 * K;
    const __half* gAl = Al + (size_t)bm * 128 * K;
    const __half* gBh = Bh + (size_t)bn * 128 * K;

    const int r0 = tid >> 2, c0 = tid & 3;

    auto load_stage = [&](int chunk, int slot) {
        const int k0 = chunk * GM_BK;
        uint32_t base = sb + slot * STAGE_B;
        #pragma unroll
        for (int i = 0; i < 2; i++) {
            int r = r0 + i * 64;
            uint32_t so = sw_off(r, c0);
            size_t go = (size_t)r * K + k0 + c0 * 8;
            cp_async16(base + OFF_AH + so, gAh + go);
            if (twoProd) cp_async16(base + OFF_AL + so, gAl + go);
            cp_async16(base + OFF_BH + so, gBh + go);
        }
        CP_COMMIT();
    };

    float acc[2][8][4];
    #pragma unroll
    for (int mt = 0; mt < 2; mt++)
        #pragma unroll
        for (int nt = 0; nt < 8; nt++)
            #pragma unroll
            for (int j = 0; j < 4; j++) acc[mt][nt][j] = 0.f;

    const int a_row = wm * 32 + (lane & 15);
    const int a_cb  = (lane >> 4) & 1;
    const int b_row = wn * 64 + (lane & 7) + ((lane & 16) ? 8 : 0);
    const int b_cb  = (lane >> 3) & 1;

    #pragma unroll
    for (int s = 0; s < STAGES - 1; s++) load_stage(s, s);

    for (int c = 0; c < NC; c++) {
        if (c + STAGES - 1 < NC) { CP_WAIT(STAGES - 2); }
        else                     { CP_WAIT(0); }
        __syncthreads();
        if (c + STAGES - 1 < NC) load_stage(c + STAGES - 1, (c + STAGES - 1) % STAGES);

        const uint32_t base = sb + (c % STAGES) * STAGE_B;

        #pragma unroll
        for (int ks = 0; ks < 2; ks++) {
            uint32_t ahf[2][4], alf[2][4];
            #pragma unroll
            for (int mt = 0; mt < 2; mt++) {
                uint32_t so = sw_off(a_row + mt * 16, 2 * ks + a_cb);
                ldmx4(ahf[mt], base + OFF_AH + so);
                if (twoProd) ldmx4(alf[mt], base + OFF_AL + so);
            }
            uint32_t bhf[8][2];
            #pragma unroll
            for (int p = 0; p < 4; p++) {
                uint32_t so = sw_off(b_row + p * 16, 2 * ks + b_cb);
                uint32_t r[4];
                ldmx4(r, base + OFF_BH + so);
                bhf[2*p][0] = r[0]; bhf[2*p][1] = r[1];
                bhf[2*p+1][0] = r[2]; bhf[2*p+1][1] = r[3];
            }
            #pragma unroll
            for (int mt = 0; mt < 2; mt++)
                #pragma unroll
                for (int nt = 0; nt < 8; nt++) {
                    mma_fp16(acc[mt][nt], ahf[mt], bhf[nt]);
                    if (twoProd) mma_fp16(acc[mt][nt], alf[mt], bhf[nt]);
                }
        }
    }

    const int erow = bm * 128 + wm * 32 + (lane >> 2);
    const int ecol = bn * 128 + wn * 64 + (lane & 3) * 2;
    #pragma unroll
    for (int mt = 0; mt < 2; mt++)
        #pragma unroll
        for (int nt = 0; nt < 8; nt++) {
            int col = ecol + nt * 8;
            float bx = bias[col], by = bias[col + 1];
            int ra = erow + mt * 16, rb = ra + 8;
            float v0 = acc[mt][nt][0] + bx, v1 = acc[mt][nt][1] + by;
            float v2 = acc[mt][nt][2] + bx, v3 = acc[mt][nt][3] + by;
            if (SPLIT) {
                // lo plane is only consumed for Q columns (head-local col < 128)
                bool isQ = (col % (3 * DK)) < DK;
                uint32_t hh, ll;
                split2h(v0, v1, hh, ll);
                *(uint32_t*)&Ch[(size_t)ra * N + col] = hh;
                if (isQ) *(uint32_t*)&Cl[(size_t)ra * N + col] = ll;
                split2h(v2, v3, hh, ll);
                *(uint32_t*)&Ch[(size_t)rb * N + col] = hh;
                if (isQ) *(uint32_t*)&Cl[(size_t)rb * N + col] = ll;
            } else {
                float2 o0 = {v0, v1}, o1 = {v2, v3};
                *(float2*)&C[(size_t)ra * N + col] = o0;
                *(float2*)&C[(size_t)rb * N + col] = o1;
            }
        }
}

// ---------------------------------------------------------------------------
// HMMA flash attention, fp16 2-product: Q = Qh+Ql (regs), K/V hi only,
// P split hi/lo in-register. 128 q-rows per CTA, 64-key tiles, double buffer.
// ---------------------------------------------------------------------------
#define AT_BQ 128
#define AT_BK 64
#define AT_NT (SEQ / AT_BK)          // 32
#define AQ_H 0
#define AQ_L 32768
#define AST(s) (65536 + (s) * 32768)
#define AK_H 0
#define AV_H 16384
#define ATTN_SMEM (65536 + 2 * 32768)   // 128 KB

__global__ __launch_bounds__(256, 1) void attn_hmma(
    const __half* __restrict__ qh_g, const __half* __restrict__ ql_g,
    __half* __restrict__ oh_g, __half* __restrict__ ol_g)
{
    extern __shared__ char smc[];
    const uint32_t sb = smem_u32(smc);
    const int tid = threadIdx.x, warp = tid >> 5, lane = tid & 31;
    const int qt = blockIdx.x, bh = blockIdx.y;
    const int b = bh >> 4, h = bh & 15;
    const size_t tok0  = (size_t)b * SEQ + qt * AT_BQ;
    const size_t ktok0 = (size_t)b * SEQ;
    const int colQ = h * 3 * DK, colK = colQ + DK, colV = colQ + 2 * DK;
    const float SCALE = 0.08838834764831845f;

    auto loadQ = [&]() {
        #pragma unroll
        for (int i = 0; i < 8; i++) {
            int idx = tid + i * 256;
            int r = idx >> 4, ch = idx & 15;
            uint32_t so = asw(r, ch);
            size_t g = (tok0 + r) * QKV_N + colQ + ch * 8;
            cp_async16(sb + AQ_H + so, qh_g + g);
            cp_async16(sb + AQ_L + so, ql_g + g);
        }
        CP_COMMIT();
    };
    auto loadK = [&](int kt, int s) {
        #pragma unroll
        for (int i = 0; i < 4; i++) {
            int idx = tid + i * 256;
            int r = idx >> 4, ch = idx & 15;
            size_t g = (ktok0 + kt * AT_BK + r) * QKV_N + colK + ch * 8;
            cp_async16(sb + AST(s) + AK_H + asw(r, ch), qh_g + g);
        }
        CP_COMMIT();
    };
    auto loadV = [&](int kt, int s) {
        #pragma unroll
        for (int i = 0; i < 4; i++) {
            int idx = tid + i * 256;
            int r = idx >> 4, ch = idx & 15;
            size_t g = (ktok0 + kt * AT_BK + r) * QKV_N + colV + ch * 8;
            cp_async16(sb + AST(s) + AV_H + asw(r, ch), qh_g + g);
        }
        CP_COMMIT();
    };

    const int aq_row = warp * 16 + (lane & 15);
    const int a_cb   = lane >> 4;
    const int bk_row = (lane & 7) + ((lane & 16) ? 8 : 0);
    const int bk_cb  = (lane >> 3) & 1;
    const int v_row  = (lane & 7) + (((lane >> 3) & 1) << 3);
    const int v_cb   = lane >> 4;

    float oacc[16][4];
    #pragma unroll
    for (int n = 0; n < 16; n++)
        #pragma unroll
        for (int j = 0; j < 4; j++) oacc[n][j] = 0.f;
    float m0 = -1e30f, m1 = -1e30f, l0 = 0.f, l1 = 0.f;

    // prologue: Q, K0, V0, K1
    loadQ();
    loadK(0, 0);
    loadV(0, 0);
    loadK(1, 1);

    // hoist Q fragments into registers
    CP_WAIT(3);
    __syncthreads();
    uint32_t qfh[8][4], qfl[8][4];
    #pragma unroll
    for (int ks = 0; ks < 8; ks++) {
        uint32_t qso = asw(aq_row, 2 * ks + a_cb);
        ldmx4(qfh[ks], sb + AQ_H + qso);
        ldmx4(qfl[ks], sb + AQ_L + qso);
    }

    for (int kt = 0; kt < AT_NT; kt++) {
        const int cur = kt & 1;

        CP_WAIT(2);              // K_kt complete
        __syncthreads();
        loadV((kt + 1) % AT_NT, cur ^ 1);   // wrap-around keeps counts exact

        const uint32_t kb = sb + AST(cur);

        // ---- S = Q K^T (2 products) ----
        float sacc[8][4];
        #pragma unroll
        for (int n = 0; n < 8; n++)
            #pragma unroll
            for (int j = 0; j < 4; j++) sacc[n][j] = 0.f;

        #pragma unroll
        for (int ks = 0; ks < 8; ks++) {
            #pragma unroll
            for (int p = 0; p < 4; p++) {
                uint32_t kh4[4];
                ldmx4(kh4, kb + AK_H + asw(p * 16 + bk_row, 2 * ks + bk_cb));
                mma_fp16(sacc[2*p],   qfh[ks], kh4);
                mma_fp16(sacc[2*p+1], qfh[ks], kh4 + 2);
                mma_fp16(sacc[2*p],   qfl[ks], kh4);
                mma_fp16(sacc[2*p+1], qfl[ks], kh4 + 2);
            }
        }

        // ---- online softmax ----
        float mx0 = -1e30f, mx1 = -1e30f;
        #pragma unroll
        for (int n = 0; n < 8; n++) {
            sacc[n][0] *= SCALE; sacc[n][1] *= SCALE;
            sacc[n][2] *= SCALE; sacc[n][3] *= SCALE;
            mx0 = fmaxf(mx0, fmaxf(sacc[n][0], sacc[n][1]));
            mx1 = fmaxf(mx1, fmaxf(sacc[n][2], sacc[n][3]));
        }
        mx0 = fmaxf(mx0, __shfl_xor_sync(0xffffffffu, mx0, 1));
        mx0 = fmaxf(mx0, __shfl_xor_sync(0xffffffffu, mx0, 2));
        mx1 = fmaxf(mx1, __shfl_xor_sync(0xffffffffu, mx1, 1));
        mx1 = fmaxf(mx1, __shfl_xor_sync(0xffffffffu, mx1, 2));
        const float mn0 = fmaxf(m0, mx0), mn1 = fmaxf(m1, mx1);

        float sum0 = 0.f, sum1 = 0.f;
        uint32_t ph[8][2], pl[8][2];
        #pragma unroll
        for (int n = 0; n < 8; n++) {
            float p00 = __expf(sacc[n][0] - mn0), p01 = __expf(sacc[n][1] - mn0);
            float p10 = __expf(sacc[n][2] - mn1), p11 = __expf(sacc[n][3] - mn1);
            sum0 += p00 + p01;
            sum1 += p10 + p11;
            split2h(p00, p01, ph[n][0], pl[n][0]);
            split2h(p10, p11, ph[n][1], pl[n][1]);
        }
        sum0 += __shfl_xor_sync(0xffffffffu, sum0, 1);
        sum0 += __shfl_xor_sync(0xffffffffu, sum0, 2);
        sum1 += __shfl_xor_sync(0xffffffffu, sum1, 1);
        sum1 += __shfl_xor_sync(0xffffffffu, sum1, 2);

        const float al0 = __expf(m0 - mn0), al1 = __expf(m1 - mn1);
        m0 = mn0; m1 = mn1;
        l0 = l0 * al0 + sum0;
        l1 = l1 * al1 + sum1;
        #pragma unroll
        for (int n = 0; n < 16; n++) {
            oacc[n][0] *= al0; oacc[n][1] *= al0;
            oacc[n][2] *= al1; oacc[n][3] *= al1;
        }

        CP_WAIT(2);              // V_kt complete
        __syncthreads();
        loadK((kt + 2) % AT_NT, cur);

        const uint32_t vb = sb + AST(cur);

        // ---- O += P V (2 products) ----
        #pragma unroll
        for (int kk = 0; kk < 4; kk++) {
            uint32_t pah[4] = {ph[2*kk][0], ph[2*kk][1], ph[2*kk+1][0], ph[2*kk+1][1]};
            uint32_t pal[4] = {pl[2*kk][0], pl[2*kk][1], pl[2*kk+1][0], pl[2*kk+1][1]};
            #pragma unroll
            for (int p = 0; p < 8; p++) {
                uint32_t vh4[4];
                ldmx4t(vh4, vb + AV_H + asw(kk * 16 + v_row, 2 * p + v_cb));
                mma_fp16(oacc[2*p],   pah, vh4);
                mma_fp16(oacc[2*p+1], pah, vh4 + 2);
                mma_fp16(oacc[2*p],   pal, vh4);
                mma_fp16(oacc[2*p+1], pal, vh4 + 2);
            }
        }
    }

    // ---- epilogue: normalize, split hi/lo, write ----
    const float inv0 = 1.f / l0, inv1 = 1.f / l1;
    const int rr = lane >> 2, c2 = (lane & 3) * 2;
    const size_t row0 = tok0 + warp * 16 + rr, row1 = row0 + 8;
    #pragma unroll
    for (int n = 0; n < 16; n++) {
        int col = h * DK + n * 8 + c2;
        uint32_t hh, ll;
        split2h(oacc[n][0] * inv0, oacc[n][1] * inv0, hh, ll);
        *(uint32_t*)&oh_g[row0 * D_MODEL + col] = hh;
        *(uint32_t*)&ol_g[row0 * D_MODEL + col] = ll;
        split2h(oacc[n][2] * inv1, oacc[n][3] * inv1, hh, ll);
        *(uint32_t*)&oh_g[row1 * D_MODEL + col] = hh;
        *(uint32_t*)&ol_g[row1 * D_MODEL + col] = ll;
    }
}

// ---------------------------------------------------------------------------
extern "C" void kernel_launch(void* const* d_in, const int* in_sizes, int n_in,
                              void* d_out, int out_size)
{
    const float* x    = (const float*)d_in[0];
    const float* Wqkv = (const float*)d_in[1];
    const float* bqkv = (const float*)d_in[2];
    const float* Wout = (const float*)d_in[3];
    const float* bout = (const float*)d_in[4];
    float* out = (float*)d_out;

    __half *qkh, *qkl, *ah, *al, *wqh, *woh;
    cudaGetSymbolAddress((void**)&qkh, g_qkv_hi);
    cudaGetSymbolAddress((void**)&qkl, g_qkv_lo);
    cudaGetSymbolAddress((void**)&ah, g_a_hi);
    cudaGetSymbolAddress((void**)&al, g_a_lo);
    cudaGetSymbolAddress((void**)&wqh, g_wq_h);
    cudaGetSymbolAddress((void**)&woh, g_wo_h);

    cudaFuncSetAttribute((const void*)gemm_hmma<true, true>,
                         cudaFuncAttributeMaxDynamicSharedMemorySize, GEMM_SMEM);
    cudaFuncSetAttribute((const void*)gemm_hmma<false, false>,
                         cudaFuncAttributeMaxDynamicSharedMemorySize, GEMM_SMEM);
    cudaFuncSetAttribute(attn_hmma, cudaFuncAttributeMaxDynamicSharedMemorySize, ATTN_SMEM);

    {
        int n4 = ROWS * D_MODEL / 4;
        split_kernel<<<(n4 + 255) / 256, 256>>>(x, ah, al, n4);
        transpose_half_kernel<<<dim3(QKV_N / 32, D_MODEL / 32), dim3(32, 8)>>>(
            Wqkv, wqh, D_MODEL, QKV_N);
        transpose_half_kernel<<<dim3(D_MODEL / 32, D_MODEL / 32), dim3(32, 8)>>>(
            Wout, woh, D_MODEL, D_MODEL);
    }

    // 1) QKV projection: Q CTAs 2-product, K/V CTAs 1-product
    gemm_hmma<true, true><<<dim3(QKV_N / 128, ROWS / 128), 256, GEMM_SMEM>>>(
        ah, al, wqh, bqkv, nullptr, qkh, qkl, ROWS, QKV_N, D_MODEL);

    // 2) attention
    attn_hmma<<<dim3(SEQ / AT_BQ, BATCH * NHEADS), 256, ATTN_SMEM>>>(qkh, qkl, ah, al);

    // 3) out-projection, fp32 output, always 2-product
    gemm_hmma<false, false><<<dim3(D_MODEL / 128, ROWS / 128), 256, GEMM_SMEM>>>(
        ah, al, woh, bout, out, nullptr, nullptr, ROWS, D_MODEL, D_MODEL);
}

// round 9
// speedup vs baseline: 1.6669x; 1.1298x over previous
#include <cuda_runtime.h>
#include <cuda_fp16.h>
#include <math.h>
#include <cstdint>

#define D_MODEL 2048
#define NHEADS  16
#define DK      128
#define BATCH   2
#define SEQ     2048
#define ROWS    (BATCH * SEQ)     // 4096
#define QKV_N   (3 * D_MODEL)     // 6144

// ---------------------------------------------------------------------------
// Scratch (device globals — no cudaMalloc allowed)
// ---------------------------------------------------------------------------
__device__ __half g_qkv_hi[ROWS * QKV_N];        // QKV hi (Q/K/V)
__device__ __half g_qkv_lo[ROWS * QKV_N];        // QKV lo (only Q cols used)
__device__ __half g_a_hi[ROWS * D_MODEL];        // x split hi, then attn-out hi
__device__ __half g_a_lo[ROWS * D_MODEL];
__device__ __half g_wq_h[QKV_N * D_MODEL];       // W_qkv^T fp16 (hi only)
__device__ __half g_wo_h[D_MODEL * D_MODEL];     // W_out^T fp16 (hi only)

// ---------------------------------------------------------------------------
// Base-target PTX helpers (virtual target is compute_103 — no tcgen05)
// ---------------------------------------------------------------------------
__device__ __forceinline__ uint32_t smem_u32(const void* p) {
    uint32_t a;
    asm("{ .reg .u64 t; cvta.to.shared.u64 t, %1; cvt.u32.u64 %0, t; }" : "=r"(a) : "l"(p));
    return a;
}
__device__ __forceinline__ void cp_async16(uint32_t saddr, const void* gaddr) {
    asm volatile("cp.async.cg.shared.global [%0], [%1], 16;" :: "r"(saddr), "l"(gaddr));
}
#define CP_COMMIT() asm volatile("cp.async.commit_group;" ::: "memory")
#define CP_WAIT(N)  asm volatile("cp.async.wait_group %0;" :: "n"(N) : "memory")

__device__ __forceinline__ void ldmx4(uint32_t* r, uint32_t addr) {
    asm volatile("ldmatrix.sync.aligned.m8n8.x4.shared.b16 {%0,%1,%2,%3}, [%4];"
                 : "=r"(r[0]), "=r"(r[1]), "=r"(r[2]), "=r"(r[3]) : "r"(addr));
}
__device__ __forceinline__ void ldmx4t(uint32_t* r, uint32_t addr) {
    asm volatile("ldmatrix.sync.aligned.m8n8.x4.trans.shared.b16 {%0,%1,%2,%3}, [%4];"
                 : "=r"(r[0]), "=r"(r[1]), "=r"(r[2]), "=r"(r[3]) : "r"(addr));
}
__device__ __forceinline__ void mma_fp16(float* d, const uint32_t* a, const uint32_t* b) {
    asm volatile(
        "mma.sync.aligned.m16n8k16.row.col.f32.f16.f16.f32 "
        "{%0,%1,%2,%3}, {%4,%5,%6,%7}, {%8,%9}, {%0,%1,%2,%3};"
        : "+f"(d[0]), "+f"(d[1]), "+f"(d[2]), "+f"(d[3])
        : "r"(a[0]), "r"(a[1]), "r"(a[2]), "r"(a[3]), "r"(b[0]), "r"(b[1]));
}

// pack 2 floats -> fp16x2 hi + fp16x2 residual-lo
__device__ __forceinline__ void split2h(float x, float y, uint32_t& h, uint32_t& l) {
    __half hx = __float2half(x), hy = __float2half(y);
    __half lx = __float2half(x - __half2float(hx));
    __half ly = __float2half(y - __half2float(hy));
    __half2 hh = __halves2half2(hx, hy);
    __half2 ll = __halves2half2(lx, ly);
    h = *(uint32_t*)&hh;
    l = *(uint32_t*)&ll;
}

// GEMM smem tile: rows of 32 fp16 (64B = 4 x 16B chunks): chunk ^= (row>>1)&3
__device__ __forceinline__ uint32_t sw_off(int r, int c) {
    return (uint32_t)(r * 64 + ((c ^ ((r >> 1) & 3)) << 4));
}
// Attention smem tile: rows of 128 fp16 (256B = 16 x 16B chunks): chunk ^= row&7
__device__ __forceinline__ uint32_t asw(int row, int ch) {
    return (uint32_t)(row * 256 + ((ch ^ (row & 7)) << 4));
}

// ---------------------------------------------------------------------------
__global__ void split_kernel(const float* __restrict__ in,
                             __half* __restrict__ hi,
                             __half* __restrict__ lo, int n4)
{
    int i = blockIdx.x * blockDim.x + threadIdx.x;
    if (i >= n4) return;
    float4 v = ((const float4*)in)[i];
    uint32_t h0, l0, h1, l1;
    split2h(v.x, v.y, h0, l0);
    split2h(v.z, v.w, h1, l1);
    ((uint32_t*)hi)[2*i]   = h0;
    ((uint32_t*)hi)[2*i+1] = h1;
    ((uint32_t*)lo)[2*i]   = l0;
    ((uint32_t*)lo)[2*i+1] = l1;
}

// W[K,N] fp32 -> Wt[N,K] fp16 (hi only)
__global__ void transpose_half_kernel(const float* __restrict__ W,
                                      __half* __restrict__ Th,
                                      int K, int N)
{
    __shared__ float t[32][33];
    int k0 = blockIdx.y * 32, n0 = blockIdx.x * 32;
    #pragma unroll
    for (int i = threadIdx.y; i < 32; i += 8)
        t[i][threadIdx.x] = W[(size_t)(k0 + i) * N + n0 + threadIdx.x];
    __syncthreads();
    #pragma unroll
    for (int i = threadIdx.y; i < 32; i += 8)
        Th[(size_t)(n0 + i) * K + k0 + threadIdx.x] = __float2half(t[threadIdx.x][i]);
}

// ---------------------------------------------------------------------------
// HMMA GEMM: C[M,N] = A[M,K] @ Bt[N,K]^T + bias
// Compile-time TWO (2-product Ah+Al vs 1-product Ah) — the per-CTA choice is
// made ONCE outside the mainloop so each path is a clean unrolled loop.
// ---------------------------------------------------------------------------
#define GM_BK    32
#define STAGES   4
#define TILE_B   8192                     // 128 rows x 64B
#define STAGE_B  (3 * TILE_B)             // Ah | Al | Bh
#define GEMM_SMEM (STAGES * STAGE_B)      // 96 KB
#define OFF_AH 0
#define OFF_AL TILE_B
#define OFF_BH (2 * TILE_B)

template<bool SPLIT, bool TWO>
__device__ __forceinline__ void gemm_body(
    const __half* __restrict__ gAh, const __half* __restrict__ gAl,
    const __half* __restrict__ gBh,
    const float* __restrict__ bias, float* __restrict__ C,
    __half* __restrict__ Ch, __half* __restrict__ Cl,
    int N, int K, int bm, int bn, uint32_t sb)
{
    const int tid  = threadIdx.x;
    const int warp = tid >> 5, lane = tid & 31;
    const int wm = warp >> 1, wn = warp & 1;
    const int NC = K / GM_BK;
    const int r0 = tid >> 2, c0 = tid & 3;

    auto load_stage = [&](int chunk, int slot) {
        const int k0 = chunk * GM_BK;
        uint32_t base = sb + slot * STAGE_B;
        #pragma unroll
        for (int i = 0; i < 2; i++) {
            int r = r0 + i * 64;
            uint32_t so = sw_off(r, c0);
            size_t go = (size_t)r * K + k0 + c0 * 8;
            cp_async16(base + OFF_AH + so, gAh + go);
            if (TWO) cp_async16(base + OFF_AL + so, gAl + go);
            cp_async16(base + OFF_BH + so, gBh + go);
        }
        CP_COMMIT();
    };

    float acc[2][8][4];
    #pragma unroll
    for (int mt = 0; mt < 2; mt++)
        #pragma unroll
        for (int nt = 0; nt < 8; nt++)
            #pragma unroll
            for (int j = 0; j < 4; j++) acc[mt][nt][j] = 0.f;

    const int a_row = wm * 32 + (lane & 15);
    const int a_cb  = (lane >> 4) & 1;
    const int b_row = wn * 64 + (lane & 7) + ((lane & 16) ? 8 : 0);
    const int b_cb  = (lane >> 3) & 1;

    #pragma unroll
    for (int s = 0; s < STAGES - 1; s++) load_stage(s, s);

    for (int c = 0; c < NC; c++) {
        if (c + STAGES - 1 < NC) { CP_WAIT(STAGES - 2); }
        else                     { CP_WAIT(0); }
        __syncthreads();
        if (c + STAGES - 1 < NC) load_stage(c + STAGES - 1, (c + STAGES - 1) % STAGES);

        const uint32_t base = sb + (c % STAGES) * STAGE_B;

        #pragma unroll
        for (int ks = 0; ks < 2; ks++) {
            uint32_t ahf[2][4], alf[2][4];
            #pragma unroll
            for (int mt = 0; mt < 2; mt++) {
                uint32_t so = sw_off(a_row + mt * 16, 2 * ks + a_cb);
                ldmx4(ahf[mt], base + OFF_AH + so);
                if (TWO) ldmx4(alf[mt], base + OFF_AL + so);
            }
            uint32_t bhf[8][2];
            #pragma unroll
            for (int p = 0; p < 4; p++) {
                uint32_t so = sw_off(b_row + p * 16, 2 * ks + b_cb);
                uint32_t r[4];
                ldmx4(r, base + OFF_BH + so);
                bhf[2*p][0] = r[0]; bhf[2*p][1] = r[1];
                bhf[2*p+1][0] = r[2]; bhf[2*p+1][1] = r[3];
            }
            #pragma unroll
            for (int mt = 0; mt < 2; mt++)
                #pragma unroll
                for (int nt = 0; nt < 8; nt++) {
                    mma_fp16(acc[mt][nt], ahf[mt], bhf[nt]);
                    if (TWO) mma_fp16(acc[mt][nt], alf[mt], bhf[nt]);
                }
        }
    }

    const int erow = bm * 128 + wm * 32 + (lane >> 2);
    const int ecol = bn * 128 + wn * 64 + (lane & 3) * 2;
    #pragma unroll
    for (int mt = 0; mt < 2; mt++)
        #pragma unroll
        for (int nt = 0; nt < 8; nt++) {
            int col = ecol + nt * 8;
            float bx = bias[col], by = bias[col + 1];
            int ra = erow + mt * 16, rb = ra + 8;
            float v0 = acc[mt][nt][0] + bx, v1 = acc[mt][nt][1] + by;
            float v2 = acc[mt][nt][2] + bx, v3 = acc[mt][nt][3] + by;
            if (SPLIT) {
                // lo plane is only consumed for Q columns (head-local col < 128)
                bool isQ = (col % (3 * DK)) < DK;
                uint32_t hh, ll;
                split2h(v0, v1, hh, ll);
                *(uint32_t*)&Ch[(size_t)ra * N + col] = hh;
                if (isQ) *(uint32_t*)&Cl[(size_t)ra * N + col] = ll;
                split2h(v2, v3, hh, ll);
                *(uint32_t*)&Ch[(size_t)rb * N + col] = hh;
                if (isQ) *(uint32_t*)&Cl[(size_t)rb * N + col] = ll;
            } else {
                float2 o0 = {v0, v1}, o1 = {v2, v3};
                *(float2*)&C[(size_t)ra * N + col] = o0;
                *(float2*)&C[(size_t)rb * N + col] = o1;
            }
        }
}

template<bool SPLIT, bool QKV_MODE>
__global__ __launch_bounds__(256, 2) void gemm_hmma(
    const __half* __restrict__ Ah, const __half* __restrict__ Al,
    const __half* __restrict__ Bh,
    const float* __restrict__ bias, float* __restrict__ C,
    __half* __restrict__ Ch, __half* __restrict__ Cl,
    int M, int N, int K)
{
    extern __shared__ char smc[];
    const uint32_t sb = smem_u32(smc);
    const int bm = blockIdx.y, bn = blockIdx.x;

    const __half* gAh = Ah + (size_t)bm * 128 * K;
    const __half* gAl = Al + (size_t)bm * 128 * K;
    const __half* gBh = Bh + (size_t)bn * 128 * K;

    if (!QKV_MODE || (bn % 3 == 0))
        gemm_body<SPLIT, true >(gAh, gAl, gBh, bias, C, Ch, Cl, N, K, bm, bn, sb);
    else
        gemm_body<SPLIT, false>(gAh, gAl, gBh, bias, C, Ch, Cl, N, K, bm, bn, sb);
}

// ---------------------------------------------------------------------------
// HMMA flash attention, fp16 2-product: Q = Qh+Ql (regs), K/V hi only,
// P split hi/lo in-register. 128 q-rows per CTA, 64-key tiles, double buffer.
// ---------------------------------------------------------------------------
#define AT_BQ 128
#define AT_BK 64
#define AT_NT (SEQ / AT_BK)          // 32
#define AQ_H 0
#define AQ_L 32768
#define AST(s) (65536 + (s) * 32768)
#define AK_H 0
#define AV_H 16384
#define ATTN_SMEM (65536 + 2 * 32768)   // 128 KB

__global__ __launch_bounds__(256, 1) void attn_hmma(
    const __half* __restrict__ qh_g, const __half* __restrict__ ql_g,
    __half* __restrict__ oh_g, __half* __restrict__ ol_g)
{
    extern __shared__ char smc[];
    const uint32_t sb = smem_u32(smc);
    const int tid = threadIdx.x, warp = tid >> 5, lane = tid & 31;
    const int qt = blockIdx.x, bh = blockIdx.y;
    const int b = bh >> 4, h = bh & 15;
    const size_t tok0  = (size_t)b * SEQ + qt * AT_BQ;
    const size_t ktok0 = (size_t)b * SEQ;
    const int colQ = h * 3 * DK, colK = colQ + DK, colV = colQ + 2 * DK;
    const float SCALE = 0.08838834764831845f;

    auto loadQ = [&]() {
        #pragma unroll
        for (int i = 0; i < 8; i++) {
            int idx = tid + i * 256;
            int r = idx >> 4, ch = idx & 15;
            uint32_t so = asw(r, ch);
            size_t g = (tok0 + r) * QKV_N + colQ + ch * 8;
            cp_async16(sb + AQ_H + so, qh_g + g);
            cp_async16(sb + AQ_L + so, ql_g + g);
        }
        CP_COMMIT();
    };
    auto loadK = [&](int kt, int s) {
        #pragma unroll
        for (int i = 0; i < 4; i++) {
            int idx = tid + i * 256;
            int r = idx >> 4, ch = idx & 15;
            size_t g = (ktok0 + kt * AT_BK + r) * QKV_N + colK + ch * 8;
            cp_async16(sb + AST(s) + AK_H + asw(r, ch), qh_g + g);
        }
        CP_COMMIT();
    };
    auto loadV = [&](int kt, int s) {
        #pragma unroll
        for (int i = 0; i < 4; i++) {
            int idx = tid + i * 256;
            int r = idx >> 4, ch = idx & 15;
            size_t g = (ktok0 + kt * AT_BK + r) * QKV_N + colV + ch * 8;
            cp_async16(sb + AST(s) + AV_H + asw(r, ch), qh_g + g);
        }
        CP_COMMIT();
    };

    const int aq_row = warp * 16 + (lane & 15);
    const int a_cb   = lane >> 4;
    const int bk_row = (lane & 7) + ((lane & 16) ? 8 : 0);
    const int bk_cb  = (lane >> 3) & 1;
    const int v_row  = (lane & 7) + (((lane >> 3) & 1) << 3);
    const int v_cb   = lane >> 4;

    float oacc[16][4];
    #pragma unroll
    for (int n = 0; n < 16; n++)
        #pragma unroll
        for (int j = 0; j < 4; j++) oacc[n][j] = 0.f;
    float m0 = -1e30f, m1 = -1e30f, l0 = 0.f, l1 = 0.f;

    // prologue: Q, K0, V0, K1
    loadQ();
    loadK(0, 0);
    loadV(0, 0);
    loadK(1, 1);

    // hoist Q fragments into registers
    CP_WAIT(3);
    __syncthreads();
    uint32_t qfh[8][4], qfl[8][4];
    #pragma unroll
    for (int ks = 0; ks < 8; ks++) {
        uint32_t qso = asw(aq_row, 2 * ks + a_cb);
        ldmx4(qfh[ks], sb + AQ_H + qso);
        ldmx4(qfl[ks], sb + AQ_L + qso);
    }

    for (int kt = 0; kt < AT_NT; kt++) {
        const int cur = kt & 1;

        CP_WAIT(2);              // K_kt complete
        __syncthreads();
        loadV((kt + 1) % AT_NT, cur ^ 1);   // wrap-around keeps counts exact

        const uint32_t kb = sb + AST(cur);

        // ---- S = Q K^T (2 products) ----
        float sacc[8][4];
        #pragma unroll
        for (int n = 0; n < 8; n++)
            #pragma unroll
            for (int j = 0; j < 4; j++) sacc[n][j] = 0.f;

        #pragma unroll
        for (int ks = 0; ks < 8; ks++) {
            #pragma unroll
            for (int p = 0; p < 4; p++) {
                uint32_t kh4[4];
                ldmx4(kh4, kb + AK_H + asw(p * 16 + bk_row, 2 * ks + bk_cb));
                mma_fp16(sacc[2*p],   qfh[ks], kh4);
                mma_fp16(sacc[2*p+1], qfh[ks], kh4 + 2);
                mma_fp16(sacc[2*p],   qfl[ks], kh4);
                mma_fp16(sacc[2*p+1], qfl[ks], kh4 + 2);
            }
        }

        // ---- online softmax ----
        float mx0 = -1e30f, mx1 = -1e30f;
        #pragma unroll
        for (int n = 0; n < 8; n++) {
            sacc[n][0] *= SCALE; sacc[n][1] *= SCALE;
            sacc[n][2] *= SCALE; sacc[n][3] *= SCALE;
            mx0 = fmaxf(mx0, fmaxf(sacc[n][0], sacc[n][1]));
            mx1 = fmaxf(mx1, fmaxf(sacc[n][2], sacc[n][3]));
        }
        mx0 = fmaxf(mx0, __shfl_xor_sync(0xffffffffu, mx0, 1));
        mx0 = fmaxf(mx0, __shfl_xor_sync(0xffffffffu, mx0, 2));
        mx1 = fmaxf(mx1, __shfl_xor_sync(0xffffffffu, mx1, 1));
        mx1 = fmaxf(mx1, __shfl_xor_sync(0xffffffffu, mx1, 2));
        const float mn0 = fmaxf(m0, mx0), mn1 = fmaxf(m1, mx1);

        float sum0 = 0.f, sum1 = 0.f;
        uint32_t ph[8][2], pl[8][2];
        #pragma unroll
        for (int n = 0; n < 8; n++) {
            float p00 = __expf(sacc[n][0] - mn0), p01 = __expf(sacc[n][1] - mn0);
            float p10 = __expf(sacc[n][2] - mn1), p11 = __expf(sacc[n][3] - mn1);
            sum0 += p00 + p01;
            sum1 += p10 + p11;
            split2h(p00, p01, ph[n][0], pl[n][0]);
            split2h(p10, p11, ph[n][1], pl[n][1]);
        }
        sum0 += __shfl_xor_sync(0xffffffffu, sum0, 1);
        sum0 += __shfl_xor_sync(0xffffffffu, sum0, 2);
        sum1 += __shfl_xor_sync(0xffffffffu, sum1, 1);
        sum1 += __shfl_xor_sync(0xffffffffu, sum1, 2);

        const float al0 = __expf(m0 - mn0), al1 = __expf(m1 - mn1);
        m0 = mn0; m1 = mn1;
        l0 = l0 * al0 + sum0;
        l1 = l1 * al1 + sum1;
        #pragma unroll
        for (int n = 0; n < 16; n++) {
            oacc[n][0] *= al0; oacc[n][1] *= al0;
            oacc[n][2] *= al1; oacc[n][3] *= al1;
        }

        CP_WAIT(2);              // V_kt complete
        __syncthreads();
        loadK((kt + 2) % AT_NT, cur);

        const uint32_t vb = sb + AST(cur);

        // ---- O += P V (2 products) ----
        #pragma unroll
        for (int kk = 0; kk < 4; kk++) {
            uint32_t pah[4] = {ph[2*kk][0], ph[2*kk][1], ph[2*kk+1][0], ph[2*kk+1][1]};
            uint32_t pal[4] = {pl[2*kk][0], pl[2*kk][1], pl[2*kk+1][0], pl[2*kk+1][1]};
            #pragma unroll
            for (int p = 0; p < 8; p++) {
                uint32_t vh4[4];
                ldmx4t(vh4, vb + AV_H + asw(kk * 16 + v_row, 2 * p + v_cb));
                mma_fp16(oacc[2*p],   pah, vh4);
                mma_fp16(oacc[2*p+1], pah, vh4 + 2);
                mma_fp16(oacc[2*p],   pal, vh4);
                mma_fp16(oacc[2*p+1], pal, vh4 + 2);
            }
        }
    }

    // ---- epilogue: normalize, split hi/lo, write ----
    const float inv0 = 1.f / l0, inv1 = 1.f / l1;
    const int rr = lane >> 2, c2 = (lane & 3) * 2;
    const size_t row0 = tok0 + warp * 16 + rr, row1 = row0 + 8;
    #pragma unroll
    for (int n = 0; n < 16; n++) {
        int col = h * DK + n * 8 + c2;
        uint32_t hh, ll;
        split2h(oacc[n][0] * inv0, oacc[n][1] * inv0, hh, ll);
        *(uint32_t*)&oh_g[row0 * D_MODEL + col] = hh;
        *(uint32_t*)&ol_g[row0 * D_MODEL + col] = ll;
        split2h(oacc[n][2] * inv1, oacc[n][3] * inv1, hh, ll);
        *(uint32_t*)&oh_g[row1 * D_MODEL + col] = hh;
        *(uint32_t*)&ol_g[row1 * D_MODEL + col] = ll;
    }
}

// ---------------------------------------------------------------------------
extern "C" void kernel_launch(void* const* d_in, const int* in_sizes, int n_in,
                              void* d_out, int out_size)
{
    const float* x    = (const float*)d_in[0];
    const float* Wqkv = (const float*)d_in[1];
    const float* bqkv = (const float*)d_in[2];
    const float* Wout = (const float*)d_in[3];
    const float* bout = (const float*)d_in[4];
    float* out = (float*)d_out;

    __half *qkh, *qkl, *ah, *al, *wqh, *woh;
    cudaGetSymbolAddress((void**)&qkh, g_qkv_hi);
    cudaGetSymbolAddress((void**)&qkl, g_qkv_lo);
    cudaGetSymbolAddress((void**)&ah, g_a_hi);
    cudaGetSymbolAddress((void**)&al, g_a_lo);
    cudaGetSymbolAddress((void**)&wqh, g_wq_h);
    cudaGetSymbolAddress((void**)&woh, g_wo_h);

    cudaFuncSetAttribute((const void*)gemm_hmma<true, true>,
                         cudaFuncAttributeMaxDynamicSharedMemorySize, GEMM_SMEM);
    cudaFuncSetAttribute((const void*)gemm_hmma<false, false>,
                         cudaFuncAttributeMaxDynamicSharedMemorySize, GEMM_SMEM);
    cudaFuncSetAttribute(attn_hmma, cudaFuncAttributeMaxDynamicSharedMemorySize, ATTN_SMEM);

    {
        int n4 = ROWS * D_MODEL / 4;
        split_kernel<<<(n4 + 255) / 256, 256>>>(x, ah, al, n4);
        transpose_half_kernel<<<dim3(QKV_N / 32, D_MODEL / 32), dim3(32, 8)>>>(
            Wqkv, wqh, D_MODEL, QKV_N);
        transpose_half_kernel<<<dim3(D_MODEL / 32, D_MODEL / 32), dim3(32, 8)>>>(
            Wout, woh, D_MODEL, D_MODEL);
    }

    // 1) QKV projection: Q CTAs 2-product, K/V CTAs 1-product (compile-time paths)
    gemm_hmma<true, true><<<dim3(QKV_N / 128, ROWS / 128), 256, GEMM_SMEM>>>(
        ah, al, wqh, bqkv, nullptr, qkh, qkl, ROWS, QKV_N, D_MODEL);

    // 2) attention
    attn_hmma<<<dim3(SEQ / AT_BQ, BATCH * NHEADS), 256, ATTN_SMEM>>>(qkh, qkl, ah, al);

    // 3) out-projection, fp32 output, always 2-product
    gemm_hmma<false, false><<<dim3(D_MODEL / 128, ROWS / 128), 256, GEMM_SMEM>>>(
        ah, al, woh, bout, out, nullptr, nullptr, ROWS, D_MODEL, D_MODEL);
}

// round 10
// speedup vs baseline: 2.2176x; 1.3304x over previous
#include <cuda_runtime.h>
#include <cuda_fp16.h>
#include <math.h>
#include <cstdint>

#define D_MODEL 2048
#define NHEADS  16
#define DK      128
#define BATCH   2
#define SEQ     2048
#define ROWS    (BATCH * SEQ)     // 4096
#define QKV_N   (3 * D_MODEL)     // 6144

// ---------------------------------------------------------------------------
// Scratch (device globals — no cudaMalloc allowed)
// ---------------------------------------------------------------------------
__device__ __half g_qkv_hi[ROWS * QKV_N];        // QKV hi (Q/K/V), hi only
__device__ __half g_a_hi[ROWS * D_MODEL];        // x hi, then attn-out hi
__device__ __half g_a_lo[ROWS * D_MODEL];        // attn-out lo (proj guard band)
__device__ __half g_wq_h[QKV_N * D_MODEL];       // W_qkv^T fp16
__device__ __half g_wo_h[D_MODEL * D_MODEL];     // W_out^T fp16

// ---------------------------------------------------------------------------
// Base-target PTX helpers (virtual target is compute_103 — no tcgen05)
// ---------------------------------------------------------------------------
__device__ __forceinline__ uint32_t smem_u32(const void* p) {
    uint32_t a;
    asm("{ .reg .u64 t; cvta.to.shared.u64 t, %1; cvt.u32.u64 %0, t; }" : "=r"(a) : "l"(p));
    return a;
}
__device__ __forceinline__ void cp_async16(uint32_t saddr, const void* gaddr) {
    asm volatile("cp.async.cg.shared.global [%0], [%1], 16;" :: "r"(saddr), "l"(gaddr));
}
#define CP_COMMIT() asm volatile("cp.async.commit_group;" ::: "memory")
#define CP_WAIT(N)  asm volatile("cp.async.wait_group %0;" :: "n"(N) : "memory")

__device__ __forceinline__ void ldmx4(uint32_t* r, uint32_t addr) {
    asm volatile("ldmatrix.sync.aligned.m8n8.x4.shared.b16 {%0,%1,%2,%3}, [%4];"
                 : "=r"(r[0]), "=r"(r[1]), "=r"(r[2]), "=r"(r[3]) : "r"(addr));
}
__device__ __forceinline__ void ldmx4t(uint32_t* r, uint32_t addr) {
    asm volatile("ldmatrix.sync.aligned.m8n8.x4.trans.shared.b16 {%0,%1,%2,%3}, [%4];"
                 : "=r"(r[0]), "=r"(r[1]), "=r"(r[2]), "=r"(r[3]) : "r"(addr));
}
__device__ __forceinline__ void mma_fp16(float* d, const uint32_t* a, const uint32_t* b) {
    asm volatile(
        "mma.sync.aligned.m16n8k16.row.col.f32.f16.f16.f32 "
        "{%0,%1,%2,%3}, {%4,%5,%6,%7}, {%8,%9}, {%0,%1,%2,%3};"
        : "+f"(d[0]), "+f"(d[1]), "+f"(d[2]), "+f"(d[3])
        : "r"(a[0]), "r"(a[1]), "r"(a[2]), "r"(a[3]), "r"(b[0]), "r"(b[1]));
}

// pack 2 floats -> fp16x2 hi (+ optional residual-lo)
__device__ __forceinline__ void split2h(float x, float y, uint32_t& h, uint32_t& l) {
    __half hx = __float2half(x), hy = __float2half(y);
    __half lx = __float2half(x - __half2float(hx));
    __half ly = __float2half(y - __half2float(hy));
    __half2 hh = __halves2half2(hx, hy);
    __half2 ll = __halves2half2(lx, ly);
    h = *(uint32_t*)&hh;
    l = *(uint32_t*)&ll;
}
__device__ __forceinline__ uint32_t pack2h(float x, float y) {
    __half2 hh = __halves2half2(__float2half(x), __float2half(y));
    return *(uint32_t*)&hh;
}

// GEMM smem tile: rows of 32 fp16 (64B = 4 x 16B chunks): chunk ^= (row>>1)&3
__device__ __forceinline__ uint32_t sw_off(int r, int c) {
    return (uint32_t)(r * 64 + ((c ^ ((r >> 1) & 3)) << 4));
}
// Attention smem tile: rows of 128 fp16 (256B = 16 x 16B chunks): chunk ^= row&7
__device__ __forceinline__ uint32_t asw(int row, int ch) {
    return (uint32_t)(row * 256 + ((ch ^ (row & 7)) << 4));
}

// ---------------------------------------------------------------------------
// fp32 -> fp16 convert (hi only; x feeds a 1-product GEMM now)
__global__ void convert_half_kernel(const float* __restrict__ in,
                                    __half* __restrict__ hi, int n4)
{
    int i = blockIdx.x * blockDim.x + threadIdx.x;
    if (i >= n4) return;
    float4 v = ((const float4*)in)[i];
    ((uint32_t*)hi)[2*i]   = pack2h(v.x, v.y);
    ((uint32_t*)hi)[2*i+1] = pack2h(v.z, v.w);
}

// W[K,N] fp32 -> Wt[N,K] fp16
__global__ void transpose_half_kernel(const float* __restrict__ W,
                                      __half* __restrict__ Th,
                                      int K, int N)
{
    __shared__ float t[32][33];
    int k0 = blockIdx.y * 32, n0 = blockIdx.x * 32;
    #pragma unroll
    for (int i = threadIdx.y; i < 32; i += 8)
        t[i][threadIdx.x] = W[(size_t)(k0 + i) * N + n0 + threadIdx.x];
    __syncthreads();
    #pragma unroll
    for (int i = threadIdx.y; i < 32; i += 8)
        Th[(size_t)(n0 + i) * K + k0 + threadIdx.x] = __float2half(t[threadIdx.x][i]);
}

// ---------------------------------------------------------------------------
// HMMA GEMM: C[M,N] = A[M,K] @ Bt[N,K]^T + bias
// TWO=true: A = Ah+Al (2 products). TWO=false: Ah only.
// SPLIT=true: fp16-hi output; SPLIT=false: fp32 output.
// ---------------------------------------------------------------------------
#define GM_BK    32
#define STAGES   4
#define TILE_B   8192                     // 128 rows x 64B
#define STAGE_B  (3 * TILE_B)             // Ah | Al | Bh
#define GEMM_SMEM (STAGES * STAGE_B)      // 96 KB
#define OFF_AH 0
#define OFF_AL TILE_B
#define OFF_BH (2 * TILE_B)

template<bool SPLIT, bool TWO>
__global__ __launch_bounds__(256, 2) void gemm_hmma(
    const __half* __restrict__ Ah, const __half* __restrict__ Al,
    const __half* __restrict__ Bh,
    const float* __restrict__ bias, float* __restrict__ C,
    __half* __restrict__ Ch,
    int M, int N, int K)
{
    extern __shared__ char smc[];
    const uint32_t sb = smem_u32(smc);
    const int tid  = threadIdx.x;
    const int warp = tid >> 5, lane = tid & 31;
    const int wm = warp >> 1, wn = warp & 1;
    const int bm = blockIdx.y, bn = blockIdx.x;
    const int NC = K / GM_BK;

    const __half* gAh = Ah + (size_t)bm * 128 * K;
    const __half* gAl = Al + (size_t)bm * 128 * K;
    const __half* gBh = Bh + (size_t)bn * 128 * K;

    const int r0 = tid >> 2, c0 = tid & 3;

    auto load_stage = [&](int chunk, int slot) {
        const int k0 = chunk * GM_BK;
        uint32_t base = sb + slot * STAGE_B;
        #pragma unroll
        for (int i = 0; i < 2; i++) {
            int r = r0 + i * 64;
            uint32_t so = sw_off(r, c0);
            size_t go = (size_t)r * K + k0 + c0 * 8;
            cp_async16(base + OFF_AH + so, gAh + go);
            if (TWO) cp_async16(base + OFF_AL + so, gAl + go);
            cp_async16(base + OFF_BH + so, gBh + go);
        }
        CP_COMMIT();
    };

    float acc[2][8][4];
    #pragma unroll
    for (int mt = 0; mt < 2; mt++)
        #pragma unroll
        for (int nt = 0; nt < 8; nt++)
            #pragma unroll
            for (int j = 0; j < 4; j++) acc[mt][nt][j] = 0.f;

    const int a_row = wm * 32 + (lane & 15);
    const int a_cb  = (lane >> 4) & 1;
    const int b_row = wn * 64 + (lane & 7) + ((lane & 16) ? 8 : 0);
    const int b_cb  = (lane >> 3) & 1;

    #pragma unroll
    for (int s = 0; s < STAGES - 1; s++) load_stage(s, s);

    for (int c = 0; c < NC; c++) {
        if (c + STAGES - 1 < NC) { CP_WAIT(STAGES - 2); }
        else                     { CP_WAIT(0); }
        __syncthreads();
        if (c + STAGES - 1 < NC) load_stage(c + STAGES - 1, (c + STAGES - 1) % STAGES);

        const uint32_t base = sb + (c % STAGES) * STAGE_B;

        #pragma unroll
        for (int ks = 0; ks < 2; ks++) {
            uint32_t ahf[2][4], alf[2][4];
            #pragma unroll
            for (int mt = 0; mt < 2; mt++) {
                uint32_t so = sw_off(a_row + mt * 16, 2 * ks + a_cb);
                ldmx4(ahf[mt], base + OFF_AH + so);
                if (TWO) ldmx4(alf[mt], base + OFF_AL + so);
            }
            uint32_t bhf[8][2];
            #pragma unroll
            for (int p = 0; p < 4; p++) {
                uint32_t so = sw_off(b_row + p * 16, 2 * ks + b_cb);
                uint32_t r[4];
                ldmx4(r, base + OFF_BH + so);
                bhf[2*p][0] = r[0]; bhf[2*p][1] = r[1];
                bhf[2*p+1][0] = r[2]; bhf[2*p+1][1] = r[3];
            }
            #pragma unroll
            for (int mt = 0; mt < 2; mt++)
                #pragma unroll
                for (int nt = 0; nt < 8; nt++) {
                    mma_fp16(acc[mt][nt], ahf[mt], bhf[nt]);
                    if (TWO) mma_fp16(acc[mt][nt], alf[mt], bhf[nt]);
                }
        }
    }

    const int erow = bm * 128 + wm * 32 + (lane >> 2);
    const int ecol = bn * 128 + wn * 64 + (lane & 3) * 2;
    #pragma unroll
    for (int mt = 0; mt < 2; mt++)
        #pragma unroll
        for (int nt = 0; nt < 8; nt++) {
            int col = ecol + nt * 8;
            float bx = bias[col], by = bias[col + 1];
            int ra = erow + mt * 16, rb = ra + 8;
            float v0 = acc[mt][nt][0] + bx, v1 = acc[mt][nt][1] + by;
            float v2 = acc[mt][nt][2] + bx, v3 = acc[mt][nt][3] + by;
            if (SPLIT) {
                *(uint32_t*)&Ch[(size_t)ra * N + col] = pack2h(v0, v1);
                *(uint32_t*)&Ch[(size_t)rb * N + col] = pack2h(v2, v3);
            } else {
                float2 o0 = {v0, v1}, o1 = {v2, v3};
                *(float2*)&C[(size_t)ra * N + col] = o0;
                *(float2*)&C[(size_t)rb * N + col] = o1;
            }
        }
}

// ---------------------------------------------------------------------------
// HMMA flash attention, fp16 1-product both GEMMs (Q/K/V/P all hi —
// the other operand's rounding already dominates each product's error).
// 128 q-rows per CTA, 64-key tiles, double buffer. 96 KB smem.
// ---------------------------------------------------------------------------
#define AT_BQ 128
#define AT_BK 64
#define AT_NT (SEQ / AT_BK)          // 32
#define AQ_H 0
#define AST(s) (32768 + (s) * 32768)
#define AK_H 0
#define AV_H 16384
#define ATTN_SMEM (32768 + 2 * 32768)   // 96 KB

__global__ __launch_bounds__(256, 1) void attn_hmma(
    const __half* __restrict__ qkv_g,
    __half* __restrict__ oh_g, __half* __restrict__ ol_g)
{
    extern __shared__ char smc[];
    const uint32_t sb = smem_u32(smc);
    const int tid = threadIdx.x, warp = tid >> 5, lane = tid & 31;
    const int qt = blockIdx.x, bh = blockIdx.y;
    const int b = bh >> 4, h = bh & 15;
    const size_t tok0  = (size_t)b * SEQ + qt * AT_BQ;
    const size_t ktok0 = (size_t)b * SEQ;
    const int colQ = h * 3 * DK, colK = colQ + DK, colV = colQ + 2 * DK;
    const float SCALE = 0.08838834764831845f;

    auto loadQ = [&]() {
        #pragma unroll
        for (int i = 0; i < 8; i++) {
            int idx = tid + i * 256;
            int r = idx >> 4, ch = idx & 15;
            size_t g = (tok0 + r) * QKV_N + colQ + ch * 8;
            cp_async16(sb + AQ_H + asw(r, ch), qkv_g + g);
        }
        CP_COMMIT();
    };
    auto loadK = [&](int kt, int s) {
        #pragma unroll
        for (int i = 0; i < 4; i++) {
            int idx = tid + i * 256;
            int r = idx >> 4, ch = idx & 15;
            size_t g = (ktok0 + kt * AT_BK + r) * QKV_N + colK + ch * 8;
            cp_async16(sb + AST(s) + AK_H + asw(r, ch), qkv_g + g);
        }
        CP_COMMIT();
    };
    auto loadV = [&](int kt, int s) {
        #pragma unroll
        for (int i = 0; i < 4; i++) {
            int idx = tid + i * 256;
            int r = idx >> 4, ch = idx & 15;
            size_t g = (ktok0 + kt * AT_BK + r) * QKV_N + colV + ch * 8;
            cp_async16(sb + AST(s) + AV_H + asw(r, ch), qkv_g + g);
        }
        CP_COMMIT();
    };

    const int aq_row = warp * 16 + (lane & 15);
    const int a_cb   = lane >> 4;
    const int bk_row = (lane & 7) + ((lane & 16) ? 8 : 0);
    const int bk_cb  = (lane >> 3) & 1;
    const int v_row  = (lane & 7) + (((lane >> 3) & 1) << 3);
    const int v_cb   = lane >> 4;

    float oacc[16][4];
    #pragma unroll
    for (int n = 0; n < 16; n++)
        #pragma unroll
        for (int j = 0; j < 4; j++) oacc[n][j] = 0.f;
    float m0 = -1e30f, m1 = -1e30f, l0 = 0.f, l1 = 0.f;

    // prologue: Q, K0, V0, K1
    loadQ();
    loadK(0, 0);
    loadV(0, 0);
    loadK(1, 1);

    // hoist Q fragments into registers
    CP_WAIT(3);
    __syncthreads();
    uint32_t qfh[8][4];
    #pragma unroll
    for (int ks = 0; ks < 8; ks++)
        ldmx4(qfh[ks], sb + AQ_H + asw(aq_row, 2 * ks + a_cb));

    for (int kt = 0; kt < AT_NT; kt++) {
        const int cur = kt & 1;

        CP_WAIT(2);              // K_kt complete
        __syncthreads();
        loadV((kt + 1) % AT_NT, cur ^ 1);   // wrap-around keeps counts exact

        const uint32_t kb = sb + AST(cur);

        // ---- S = Q K^T (1 product) ----
        float sacc[8][4];
        #pragma unroll
        for (int n = 0; n < 8; n++)
            #pragma unroll
            for (int j = 0; j < 4; j++) sacc[n][j] = 0.f;

        #pragma unroll
        for (int ks = 0; ks < 8; ks++) {
            #pragma unroll
            for (int p = 0; p < 4; p++) {
                uint32_t kh4[4];
                ldmx4(kh4, kb + AK_H + asw(p * 16 + bk_row, 2 * ks + bk_cb));
                mma_fp16(sacc[2*p],   qfh[ks], kh4);
                mma_fp16(sacc[2*p+1], qfh[ks], kh4 + 2);
            }
        }

        // ---- online softmax ----
        float mx0 = -1e30f, mx1 = -1e30f;
        #pragma unroll
        for (int n = 0; n < 8; n++) {
            sacc[n][0] *= SCALE; sacc[n][1] *= SCALE;
            sacc[n][2] *= SCALE; sacc[n][3] *= SCALE;
            mx0 = fmaxf(mx0, fmaxf(sacc[n][0], sacc[n][1]));
            mx1 = fmaxf(mx1, fmaxf(sacc[n][2], sacc[n][3]));
        }
        mx0 = fmaxf(mx0, __shfl_xor_sync(0xffffffffu, mx0, 1));
        mx0 = fmaxf(mx0, __shfl_xor_sync(0xffffffffu, mx0, 2));
        mx1 = fmaxf(mx1, __shfl_xor_sync(0xffffffffu, mx1, 1));
        mx1 = fmaxf(mx1, __shfl_xor_sync(0xffffffffu, mx1, 2));
        const float mn0 = fmaxf(m0, mx0), mn1 = fmaxf(m1, mx1);

        float sum0 = 0.f, sum1 = 0.f;
        uint32_t ph[8][2];
        #pragma unroll
        for (int n = 0; n < 8; n++) {
            float p00 = __expf(sacc[n][0] - mn0), p01 = __expf(sacc[n][1] - mn0);
            float p10 = __expf(sacc[n][2] - mn1), p11 = __expf(sacc[n][3] - mn1);
            sum0 += p00 + p01;
            sum1 += p10 + p11;
            ph[n][0] = pack2h(p00, p01);
            ph[n][1] = pack2h(p10, p11);
        }
        sum0 += __shfl_xor_sync(0xffffffffu, sum0, 1);
        sum0 += __shfl_xor_sync(0xffffffffu, sum0, 2);
        sum1 += __shfl_xor_sync(0xffffffffu, sum1, 1);
        sum1 += __shfl_xor_sync(0xffffffffu, sum1, 2);

        const float al0 = __expf(m0 - mn0), al1 = __expf(m1 - mn1);
        m0 = mn0; m1 = mn1;
        l0 = l0 * al0 + sum0;
        l1 = l1 * al1 + sum1;
        #pragma unroll
        for (int n = 0; n < 16; n++) {
            oacc[n][0] *= al0; oacc[n][1] *= al0;
            oacc[n][2] *= al1; oacc[n][3] *= al1;
        }

        CP_WAIT(2);              // V_kt complete
        __syncthreads();
        loadK((kt + 2) % AT_NT, cur);

        const uint32_t vb = sb + AST(cur);

        // ---- O += P V (1 product) ----
        #pragma unroll
        for (int kk = 0; kk < 4; kk++) {
            uint32_t pah[4] = {ph[2*kk][0], ph[2*kk][1], ph[2*kk+1][0], ph[2*kk+1][1]};
            #pragma unroll
            for (int p = 0; p < 8; p++) {
                uint32_t vh4[4];
                ldmx4t(vh4, vb + AV_H + asw(kk * 16 + v_row, 2 * p + v_cb));
                mma_fp16(oacc[2*p],   pah, vh4);
                mma_fp16(oacc[2*p+1], pah, vh4 + 2);
            }
        }
    }

    // ---- epilogue: normalize, split hi/lo (proj guard band), write ----
    const float inv0 = 1.f / l0, inv1 = 1.f / l1;
    const int rr = lane >> 2, c2 = (lane & 3) * 2;
    const size_t row0 = tok0 + warp * 16 + rr, row1 = row0 + 8;
    #pragma unroll
    for (int n = 0; n < 16; n++) {
        int col = h * DK + n * 8 + c2;
        uint32_t hh, ll;
        split2h(oacc[n][0] * inv0, oacc[n][1] * inv0, hh, ll);
        *(uint32_t*)&oh_g[row0 * D_MODEL + col] = hh;
        *(uint32_t*)&ol_g[row0 * D_MODEL + col] = ll;
        split2h(oacc[n][2] * inv1, oacc[n][3] * inv1, hh, ll);
        *(uint32_t*)&oh_g[row1 * D_MODEL + col] = hh;
        *(uint32_t*)&ol_g[row1 * D_MODEL + col] = ll;
    }
}

// ---------------------------------------------------------------------------
extern "C" void kernel_launch(void* const* d_in, const int* in_sizes, int n_in,
                              void* d_out, int out_size)
{
    const float* x    = (const float*)d_in[0];
    const float* Wqkv = (const float*)d_in[1];
    const float* bqkv = (const float*)d_in[2];
    const float* Wout = (const float*)d_in[3];
    const float* bout = (const float*)d_in[4];
    float* out = (float*)d_out;

    __half *qkh, *ah, *al, *wqh, *woh;
    cudaGetSymbolAddress((void**)&qkh, g_qkv_hi);
    cudaGetSymbolAddress((void**)&ah, g_a_hi);
    cudaGetSymbolAddress((void**)&al, g_a_lo);
    cudaGetSymbolAddress((void**)&wqh, g_wq_h);
    cudaGetSymbolAddress((void**)&woh, g_wo_h);

    cudaFuncSetAttribute((const void*)gemm_hmma<true, false>,
                         cudaFuncAttributeMaxDynamicSharedMemorySize, GEMM_SMEM);
    cudaFuncSetAttribute((const void*)gemm_hmma<false, true>,
                         cudaFuncAttributeMaxDynamicSharedMemorySize, GEMM_SMEM);
    cudaFuncSetAttribute(attn_hmma, cudaFuncAttributeMaxDynamicSharedMemorySize, ATTN_SMEM);

    {
        int n4 = ROWS * D_MODEL / 4;
        convert_half_kernel<<<(n4 + 255) / 256, 256>>>(x, ah, n4);
        transpose_half_kernel<<<dim3(QKV_N / 32, D_MODEL / 32), dim3(32, 8)>>>(
            Wqkv, wqh, D_MODEL, QKV_N);
        transpose_half_kernel<<<dim3(D_MODEL / 32, D_MODEL / 32), dim3(32, 8)>>>(
            Wout, woh, D_MODEL, D_MODEL);
    }

    // 1) QKV projection: 1-product, fp16-hi output
    gemm_hmma<true, false><<<dim3(QKV_N / 128, ROWS / 128), 256, GEMM_SMEM>>>(
        ah, ah, wqh, bqkv, nullptr, qkh, ROWS, QKV_N, D_MODEL);

    // 2) attention (1-product S and PV), writes attn-out hi+lo
    attn_hmma<<<dim3(SEQ / AT_BQ, BATCH * NHEADS), 256, ATTN_SMEM>>>(qkh, ah, al);

    // 3) out-projection: 2-product (A = attn-out hi+lo), fp32 output
    gemm_hmma<false, true><<<dim3(D_MODEL / 128, ROWS / 128), 256, GEMM_SMEM>>>(
        ah, al, woh, bout, out, nullptr, ROWS, D_MODEL, D_MODEL);
}

// round 11
// speedup vs baseline: 2.5452x; 1.1477x over previous
#include <cuda_runtime.h>
#include <cuda_fp16.h>
#include <math.h>
#include <cstdint>

#define D_MODEL 2048
#define NHEADS  16
#define DK      128
#define BATCH   2
#define SEQ     2048
#define ROWS    (BATCH * SEQ)     // 4096
#define QKV_N   (3 * D_MODEL)     // 6144

// ---------------------------------------------------------------------------
// Scratch (device globals — no cudaMalloc allowed)
// ---------------------------------------------------------------------------
__device__ __half g_qkv_hi[ROWS * QKV_N];        // QKV (fp16)
__device__ __half g_a_hi[ROWS * D_MODEL];        // x fp16, then attn-out fp16
__device__ __half g_wq_h[QKV_N * D_MODEL];       // W_qkv^T fp16
__device__ __half g_wo_h[D_MODEL * D_MODEL];     // W_out^T fp16

// ---------------------------------------------------------------------------
// Base-target PTX helpers (virtual target is compute_103 — no tcgen05)
// ---------------------------------------------------------------------------
__device__ __forceinline__ uint32_t smem_u32(const void* p) {
    uint32_t a;
    asm("{ .reg .u64 t; cvta.to.shared.u64 t, %1; cvt.u32.u64 %0, t; }" : "=r"(a) : "l"(p));
    return a;
}
__device__ __forceinline__ void cp_async16(uint32_t saddr, const void* gaddr) {
    asm volatile("cp.async.cg.shared.global [%0], [%1], 16;" :: "r"(saddr), "l"(gaddr));
}
#define CP_COMMIT() asm volatile("cp.async.commit_group;" ::: "memory")
#define CP_WAIT(N)  asm volatile("cp.async.wait_group %0;" :: "n"(N) : "memory")

__device__ __forceinline__ void ldmx4(uint32_t* r, uint32_t addr) {
    asm volatile("ldmatrix.sync.aligned.m8n8.x4.shared.b16 {%0,%1,%2,%3}, [%4];"
                 : "=r"(r[0]), "=r"(r[1]), "=r"(r[2]), "=r"(r[3]) : "r"(addr));
}
__device__ __forceinline__ void ldmx4t(uint32_t* r, uint32_t addr) {
    asm volatile("ldmatrix.sync.aligned.m8n8.x4.trans.shared.b16 {%0,%1,%2,%3}, [%4];"
                 : "=r"(r[0]), "=r"(r[1]), "=r"(r[2]), "=r"(r[3]) : "r"(addr));
}
__device__ __forceinline__ void mma_fp16(float* d, const uint32_t* a, const uint32_t* b) {
    asm volatile(
        "mma.sync.aligned.m16n8k16.row.col.f32.f16.f16.f32 "
        "{%0,%1,%2,%3}, {%4,%5,%6,%7}, {%8,%9}, {%0,%1,%2,%3};"
        : "+f"(d[0]), "+f"(d[1]), "+f"(d[2]), "+f"(d[3])
        : "r"(a[0]), "r"(a[1]), "r"(a[2]), "r"(a[3]), "r"(b[0]), "r"(b[1]));
}

__device__ __forceinline__ uint32_t pack2h(float x, float y) {
    __half2 hh = __halves2half2(__float2half(x), __float2half(y));
    return *(uint32_t*)&hh;
}

// GEMM smem tile: rows of 32 fp16 (64B = 4 x 16B chunks): chunk ^= (row>>1)&3
__device__ __forceinline__ uint32_t sw_off(int r, int c) {
    return (uint32_t)(r * 64 + ((c ^ ((r >> 1) & 3)) << 4));
}
// Attention smem tile: rows of 128 fp16 (256B = 16 x 16B chunks): chunk ^= row&7
__device__ __forceinline__ uint32_t asw(int row, int ch) {
    return (uint32_t)(row * 256 + ((ch ^ (row & 7)) << 4));
}

// ---------------------------------------------------------------------------
// fp32 -> fp16 convert
__global__ void convert_half_kernel(const float* __restrict__ in,
                                    __half* __restrict__ hi, int n4)
{
    int i = blockIdx.x * blockDim.x + threadIdx.x;
    if (i >= n4) return;
    float4 v = ((const float4*)in)[i];
    ((uint32_t*)hi)[2*i]   = pack2h(v.x, v.y);
    ((uint32_t*)hi)[2*i+1] = pack2h(v.z, v.w);
}

// W[K,N] fp32 -> Wt[N,K] fp16
__global__ void transpose_half_kernel(const float* __restrict__ W,
                                      __half* __restrict__ Th,
                                      int K, int N)
{
    __shared__ float t[32][33];
    int k0 = blockIdx.y * 32, n0 = blockIdx.x * 32;
    #pragma unroll
    for (int i = threadIdx.y; i < 32; i += 8)
        t[i][threadIdx.x] = W[(size_t)(k0 + i) * N + n0 + threadIdx.x];
    __syncthreads();
    #pragma unroll
    for (int i = threadIdx.y; i < 32; i += 8)
        Th[(size_t)(n0 + i) * K + k0 + threadIdx.x] = __float2half(t[threadIdx.x][i]);
}

// ---------------------------------------------------------------------------
// HMMA GEMM: C[M,N] = A[M,K] @ Bt[N,K]^T + bias   (fp16 x fp16, fp32 acc)
// SPLIT=true: fp16 output; SPLIT=false: fp32 output.
// CTA 128x128, BK=32, multi-stage cp.async pipeline, 8 warps (4x2).
// ---------------------------------------------------------------------------
#define GM_BK    32
#define STAGES   4
#define TILE_B   8192                     // 128 rows x 64B
#define STAGE_B  (3 * TILE_B)             // Ah | (unused) | Bh  (layout kept stable)
#define GEMM_SMEM (STAGES * STAGE_B)      // 96 KB
#define OFF_AH 0
#define OFF_BH (2 * TILE_B)

template<bool SPLIT>
__global__ __launch_bounds__(256, 2) void gemm_hmma(
    const __half* __restrict__ Ah,
    const __half* __restrict__ Bh,
    const float* __restrict__ bias, float* __restrict__ C,
    __half* __restrict__ Ch,
    int M, int N, int K)
{
    extern __shared__ char smc[];
    const uint32_t sb = smem_u32(smc);
    const int tid  = threadIdx.x;
    const int warp = tid >> 5, lane = tid & 31;
    const int wm = warp >> 1, wn = warp & 1;
    const int bm = blockIdx.y, bn = blockIdx.x;
    const int NC = K / GM_BK;

    const __half* gAh = Ah + (size_t)bm * 128 * K;
    const __half* gBh = Bh + (size_t)bn * 128 * K;

    const int r0 = tid >> 2, c0 = tid & 3;

    auto load_stage = [&](int chunk, int slot) {
        const int k0 = chunk * GM_BK;
        uint32_t base = sb + slot * STAGE_B;
        #pragma unroll
        for (int i = 0; i < 2; i++) {
            int r = r0 + i * 64;
            uint32_t so = sw_off(r, c0);
            size_t go = (size_t)r * K + k0 + c0 * 8;
            cp_async16(base + OFF_AH + so, gAh + go);
            cp_async16(base + OFF_BH + so, gBh + go);
        }
        CP_COMMIT();
    };

    float acc[2][8][4];
    #pragma unroll
    for (int mt = 0; mt < 2; mt++)
        #pragma unroll
        for (int nt = 0; nt < 8; nt++)
            #pragma unroll
            for (int j = 0; j < 4; j++) acc[mt][nt][j] = 0.f;

    const int a_row = wm * 32 + (lane & 15);
    const int a_cb  = (lane >> 4) & 1;
    const int b_row = wn * 64 + (lane & 7) + ((lane & 16) ? 8 : 0);
    const int b_cb  = (lane >> 3) & 1;

    #pragma unroll
    for (int s = 0; s < STAGES - 1; s++) load_stage(s, s);

    for (int c = 0; c < NC; c++) {
        if (c + STAGES - 1 < NC) { CP_WAIT(STAGES - 2); }
        else                     { CP_WAIT(0); }
        __syncthreads();
        if (c + STAGES - 1 < NC) load_stage(c + STAGES - 1, (c + STAGES - 1) % STAGES);

        const uint32_t base = sb + (c % STAGES) * STAGE_B;

        #pragma unroll
        for (int ks = 0; ks < 2; ks++) {
            uint32_t ahf[2][4];
            #pragma unroll
            for (int mt = 0; mt < 2; mt++)
                ldmx4(ahf[mt], base + OFF_AH + sw_off(a_row + mt * 16, 2 * ks + a_cb));
            uint32_t bhf[8][2];
            #pragma unroll
            for (int p = 0; p < 4; p++) {
                uint32_t r[4];
                ldmx4(r, base + OFF_BH + sw_off(b_row + p * 16, 2 * ks + b_cb));
                bhf[2*p][0] = r[0]; bhf[2*p][1] = r[1];
                bhf[2*p+1][0] = r[2]; bhf[2*p+1][1] = r[3];
            }
            #pragma unroll
            for (int mt = 0; mt < 2; mt++)
                #pragma unroll
                for (int nt = 0; nt < 8; nt++)
                    mma_fp16(acc[mt][nt], ahf[mt], bhf[nt]);
        }
    }

    const int erow = bm * 128 + wm * 32 + (lane >> 2);
    const int ecol = bn * 128 + wn * 64 + (lane & 3) * 2;
    #pragma unroll
    for (int mt = 0; mt < 2; mt++)
        #pragma unroll
        for (int nt = 0; nt < 8; nt++) {
            int col = ecol + nt * 8;
            float bx = bias[col], by = bias[col + 1];
            int ra = erow + mt * 16, rb = ra + 8;
            float v0 = acc[mt][nt][0] + bx, v1 = acc[mt][nt][1] + by;
            float v2 = acc[mt][nt][2] + bx, v3 = acc[mt][nt][3] + by;
            if (SPLIT) {
                *(uint32_t*)&Ch[(size_t)ra * N + col] = pack2h(v0, v1);
                *(uint32_t*)&Ch[(size_t)rb * N + col] = pack2h(v2, v3);
            } else {
                float2 o0 = {v0, v1}, o1 = {v2, v3};
                *(float2*)&C[(size_t)ra * N + col] = o0;
                *(float2*)&C[(size_t)rb * N + col] = o1;
            }
        }
}

// ---------------------------------------------------------------------------
// HMMA flash attention, fp16 single-product GEMMs, fp32 online softmax.
// 128 q-rows per CTA, 64-key tiles, double buffer. 96 KB smem.
// ---------------------------------------------------------------------------
#define AT_BQ 128
#define AT_BK 64
#define AT_NT (SEQ / AT_BK)          // 32
#define AQ_H 0
#define AST(s) (32768 + (s) * 32768)
#define AK_H 0
#define AV_H 16384
#define ATTN_SMEM (32768 + 2 * 32768)   // 96 KB

__global__ __launch_bounds__(256, 1) void attn_hmma(
    const __half* __restrict__ qkv_g,
    __half* __restrict__ oh_g)
{
    extern __shared__ char smc[];
    const uint32_t sb = smem_u32(smc);
    const int tid = threadIdx.x, warp = tid >> 5, lane = tid & 31;
    const int qt = blockIdx.x, bh = blockIdx.y;
    const int b = bh >> 4, h = bh & 15;
    const size_t tok0  = (size_t)b * SEQ + qt * AT_BQ;
    const size_t ktok0 = (size_t)b * SEQ;
    const int colQ = h * 3 * DK, colK = colQ + DK, colV = colQ + 2 * DK;
    const float SCALE = 0.08838834764831845f;

    auto loadQ = [&]() {
        #pragma unroll
        for (int i = 0; i < 8; i++) {
            int idx = tid + i * 256;
            int r = idx >> 4, ch = idx & 15;
            size_t g = (tok0 + r) * QKV_N + colQ + ch * 8;
            cp_async16(sb + AQ_H + asw(r, ch), qkv_g + g);
        }
        CP_COMMIT();
    };
    auto loadK = [&](int kt, int s) {
        #pragma unroll
        for (int i = 0; i < 4; i++) {
            int idx = tid + i * 256;
            int r = idx >> 4, ch = idx & 15;
            size_t g = (ktok0 + kt * AT_BK + r) * QKV_N + colK + ch * 8;
            cp_async16(sb + AST(s) + AK_H + asw(r, ch), qkv_g + g);
        }
        CP_COMMIT();
    };
    auto loadV = [&](int kt, int s) {
        #pragma unroll
        for (int i = 0; i < 4; i++) {
            int idx = tid + i * 256;
            int r = idx >> 4, ch = idx & 15;
            size_t g = (ktok0 + kt * AT_BK + r) * QKV_N + colV + ch * 8;
            cp_async16(sb + AST(s) + AV_H + asw(r, ch), qkv_g + g);
        }
        CP_COMMIT();
    };

    const int aq_row = warp * 16 + (lane & 15);
    const int a_cb   = lane >> 4;
    const int bk_row = (lane & 7) + ((lane & 16) ? 8 : 0);
    const int bk_cb  = (lane >> 3) & 1;
    const int v_row  = (lane & 7) + (((lane >> 3) & 1) << 3);
    const int v_cb   = lane >> 4;

    float oacc[16][4];
    #pragma unroll
    for (int n = 0; n < 16; n++)
        #pragma unroll
        for (int j = 0; j < 4; j++) oacc[n][j] = 0.f;
    float m0 = -1e30f, m1 = -1e30f, l0 = 0.f, l1 = 0.f;

    // prologue: Q, K0, V0, K1
    loadQ();
    loadK(0, 0);
    loadV(0, 0);
    loadK(1, 1);

    // hoist Q fragments into registers
    CP_WAIT(3);
    __syncthreads();
    uint32_t qfh[8][4];
    #pragma unroll
    for (int ks = 0; ks < 8; ks++)
        ldmx4(qfh[ks], sb + AQ_H + asw(aq_row, 2 * ks + a_cb));

    for (int kt = 0; kt < AT_NT; kt++) {
        const int cur = kt & 1;

        CP_WAIT(2);              // K_kt complete
        __syncthreads();
        loadV((kt + 1) % AT_NT, cur ^ 1);   // wrap-around keeps counts exact

        const uint32_t kb = sb + AST(cur);

        // ---- S = Q K^T ----
        float sacc[8][4];
        #pragma unroll
        for (int n = 0; n < 8; n++)
            #pragma unroll
            for (int j = 0; j < 4; j++) sacc[n][j] = 0.f;

        #pragma unroll
        for (int ks = 0; ks < 8; ks++) {
            #pragma unroll
            for (int p = 0; p < 4; p++) {
                uint32_t kh4[4];
                ldmx4(kh4, kb + AK_H + asw(p * 16 + bk_row, 2 * ks + bk_cb));
                mma_fp16(sacc[2*p],   qfh[ks], kh4);
                mma_fp16(sacc[2*p+1], qfh[ks], kh4 + 2);
            }
        }

        // ---- online softmax ----
        float mx0 = -1e30f, mx1 = -1e30f;
        #pragma unroll
        for (int n = 0; n < 8; n++) {
            sacc[n][0] *= SCALE; sacc[n][1] *= SCALE;
            sacc[n][2] *= SCALE; sacc[n][3] *= SCALE;
            mx0 = fmaxf(mx0, fmaxf(sacc[n][0], sacc[n][1]));
            mx1 = fmaxf(mx1, fmaxf(sacc[n][2], sacc[n][3]));
        }
        mx0 = fmaxf(mx0, __shfl_xor_sync(0xffffffffu, mx0, 1));
        mx0 = fmaxf(mx0, __shfl_xor_sync(0xffffffffu, mx0, 2));
        mx1 = fmaxf(mx1, __shfl_xor_sync(0xffffffffu, mx1, 1));
        mx1 = fmaxf(mx1, __shfl_xor_sync(0xffffffffu, mx1, 2));
        const float mn0 = fmaxf(m0, mx0), mn1 = fmaxf(m1, mx1);

        float sum0 = 0.f, sum1 = 0.f;
        uint32_t ph[8][2];
        #pragma unroll
        for (int n = 0; n < 8; n++) {
            float p00 = __expf(sacc[n][0] - mn0), p01 = __expf(sacc[n][1] - mn0);
            float p10 = __expf(sacc[n][2] - mn1), p11 = __expf(sacc[n][3] - mn1);
            sum0 += p00 + p01;
            sum1 += p10 + p11;
            ph[n][0] = pack2h(p00, p01);
            ph[n][1] = pack2h(p10, p11);
        }
        sum0 += __shfl_xor_sync(0xffffffffu, sum0, 1);
        sum0 += __shfl_xor_sync(0xffffffffu, sum0, 2);
        sum1 += __shfl_xor_sync(0xffffffffu, sum1, 1);
        sum1 += __shfl_xor_sync(0xffffffffu, sum1, 2);

        const float al0 = __expf(m0 - mn0), al1 = __expf(m1 - mn1);
        m0 = mn0; m1 = mn1;
        l0 = l0 * al0 + sum0;
        l1 = l1 * al1 + sum1;
        #pragma unroll
        for (int n = 0; n < 16; n++) {
            oacc[n][0] *= al0; oacc[n][1] *= al0;
            oacc[n][2] *= al1; oacc[n][3] *= al1;
        }

        CP_WAIT(2);              // V_kt complete
        __syncthreads();
        loadK((kt + 2) % AT_NT, cur);

        const uint32_t vb = sb + AST(cur);

        // ---- O += P V ----
        #pragma unroll
        for (int kk = 0; kk < 4; kk++) {
            uint32_t pah[4] = {ph[2*kk][0], ph[2*kk][1], ph[2*kk+1][0], ph[2*kk+1][1]};
            #pragma unroll
            for (int p = 0; p < 8; p++) {
                uint32_t vh4[4];
                ldmx4t(vh4, vb + AV_H + asw(kk * 16 + v_row, 2 * p + v_cb));
                mma_fp16(oacc[2*p],   pah, vh4);
                mma_fp16(oacc[2*p+1], pah, vh4 + 2);
            }
        }
    }

    // ---- epilogue: normalize, write fp16 ----
    const float inv0 = 1.f / l0, inv1 = 1.f / l1;
    const int rr = lane >> 2, c2 = (lane & 3) * 2;
    const size_t row0 = tok0 + warp * 16 + rr, row1 = row0 + 8;
    #pragma unroll
    for (int n = 0; n < 16; n++) {
        int col = h * DK + n * 8 + c2;
        *(uint32_t*)&oh_g[row0 * D_MODEL + col] = pack2h(oacc[n][0] * inv0, oacc[n][1] * inv0);
        *(uint32_t*)&oh_g[row1 * D_MODEL + col] = pack2h(oacc[n][2] * inv1, oacc[n][3] * inv1);
    }
}

// ---------------------------------------------------------------------------
extern "C" void kernel_launch(void* const* d_in, const int* in_sizes, int n_in,
                              void* d_out, int out_size)
{
    const float* x    = (const float*)d_in[0];
    const float* Wqkv = (const float*)d_in[1];
    const float* bqkv = (const float*)d_in[2];
    const float* Wout = (const float*)d_in[3];
    const float* bout = (const float*)d_in[4];
    float* out = (float*)d_out;

    __half *qkh, *ah, *wqh, *woh;
    cudaGetSymbolAddress((void**)&qkh, g_qkv_hi);
    cudaGetSymbolAddress((void**)&ah, g_a_hi);
    cudaGetSymbolAddress((void**)&wqh, g_wq_h);
    cudaGetSymbolAddress((void**)&woh, g_wo_h);

    cudaFuncSetAttribute((const void*)gemm_hmma<true>,
                         cudaFuncAttributeMaxDynamicSharedMemorySize, GEMM_SMEM);
    cudaFuncSetAttribute((const void*)gemm_hmma<false>,
                         cudaFuncAttributeMaxDynamicSharedMemorySize, GEMM_SMEM);
    cudaFuncSetAttribute(attn_hmma, cudaFuncAttributeMaxDynamicSharedMemorySize, ATTN_SMEM);

    {
        int n4 = ROWS * D_MODEL / 4;
        convert_half_kernel<<<(n4 + 255) / 256, 256>>>(x, ah, n4);
        transpose_half_kernel<<<dim3(QKV_N / 32, D_MODEL / 32), dim3(32, 8)>>>(
            Wqkv, wqh, D_MODEL, QKV_N);
        transpose_half_kernel<<<dim3(D_MODEL / 32, D_MODEL / 32), dim3(32, 8)>>>(
            Wout, woh, D_MODEL, D_MODEL);
    }

    // 1) QKV projection: fp16 output
    gemm_hmma<true><<<dim3(QKV_N / 128, ROWS / 128), 256, GEMM_SMEM>>>(
        ah, wqh, bqkv, nullptr, qkh, ROWS, QKV_N, D_MODEL);

    // 2) attention -> attn-out fp16
    attn_hmma<<<dim3(SEQ / AT_BQ, BATCH * NHEADS), 256, ATTN_SMEM>>>(qkh, ah);

    // 3) out-projection: fp32 output
    gemm_hmma<false><<<dim3(D_MODEL / 128, ROWS / 128), 256, GEMM_SMEM>>>(
        ah, woh, bout, out, nullptr, ROWS, D_MODEL, D_MODEL);
}

// round 12
// speedup vs baseline: 2.6738x; 1.0505x over previous
#include <cuda_runtime.h>
#include <cuda_fp16.h>
#include <math.h>
#include <cstdint>

#define D_MODEL 2048
#define NHEADS  16
#define DK      128
#define BATCH   2
#define SEQ     2048
#define ROWS    (BATCH * SEQ)     // 4096
#define QKV_N   (3 * D_MODEL)     // 6144

// ---------------------------------------------------------------------------
// Scratch (device globals — no cudaMalloc allowed)
// ---------------------------------------------------------------------------
__device__ __half g_qkv_hi[ROWS * QKV_N];        // QKV (fp16)
__device__ __half g_a_hi[ROWS * D_MODEL];        // x fp16, then attn-out fp16
__device__ __half g_wq_h[QKV_N * D_MODEL];       // W_qkv^T fp16
__device__ __half g_wo_h[D_MODEL * D_MODEL];     // W_out^T fp16

// ---------------------------------------------------------------------------
// Base-target PTX helpers (virtual target is compute_103 — no tcgen05)
// ---------------------------------------------------------------------------
__device__ __forceinline__ uint32_t smem_u32(const void* p) {
    uint32_t a;
    asm("{ .reg .u64 t; cvta.to.shared.u64 t, %1; cvt.u32.u64 %0, t; }" : "=r"(a) : "l"(p));
    return a;
}
__device__ __forceinline__ void cp_async16(uint32_t saddr, const void* gaddr) {
    asm volatile("cp.async.cg.shared.global [%0], [%1], 16;" :: "r"(saddr), "l"(gaddr));
}
#define CP_COMMIT() asm volatile("cp.async.commit_group;" ::: "memory")
#define CP_WAIT(N)  asm volatile("cp.async.wait_group %0;" :: "n"(N) : "memory")

__device__ __forceinline__ void ldmx4(uint32_t* r, uint32_t addr) {
    asm volatile("ldmatrix.sync.aligned.m8n8.x4.shared.b16 {%0,%1,%2,%3}, [%4];"
                 : "=r"(r[0]), "=r"(r[1]), "=r"(r[2]), "=r"(r[3]) : "r"(addr));
}
__device__ __forceinline__ void ldmx4t(uint32_t* r, uint32_t addr) {
    asm volatile("ldmatrix.sync.aligned.m8n8.x4.trans.shared.b16 {%0,%1,%2,%3}, [%4];"
                 : "=r"(r[0]), "=r"(r[1]), "=r"(r[2]), "=r"(r[3]) : "r"(addr));
}
__device__ __forceinline__ void mma_fp16(float* d, const uint32_t* a, const uint32_t* b) {
    asm volatile(
        "mma.sync.aligned.m16n8k16.row.col.f32.f16.f16.f32 "
        "{%0,%1,%2,%3}, {%4,%5,%6,%7}, {%8,%9}, {%0,%1,%2,%3};"
        : "+f"(d[0]), "+f"(d[1]), "+f"(d[2]), "+f"(d[3])
        : "r"(a[0]), "r"(a[1]), "r"(a[2]), "r"(a[3]), "r"(b[0]), "r"(b[1]));
}

__device__ __forceinline__ uint32_t pack2h(float x, float y) {
    __half2 hh = __halves2half2(__float2half(x), __float2half(y));
    return *(uint32_t*)&hh;
}

// 128B-row smem tile swizzle (8 x 16B chunks per row): chunk ^= row&7
__device__ __forceinline__ uint32_t gsw(int r, int c) {
    return (uint32_t)(r * 128 + ((c ^ (r & 7)) << 4));
}
// Attention smem tile: rows of 128 fp16 (256B = 16 x 16B chunks): chunk ^= row&7
__device__ __forceinline__ uint32_t asw(int row, int ch) {
    return (uint32_t)(row * 256 + ((ch ^ (row & 7)) << 4));
}

// ---------------------------------------------------------------------------
// fp32 -> fp16 convert
__global__ void convert_half_kernel(const float* __restrict__ in,
                                    __half* __restrict__ hi, int n4)
{
    int i = blockIdx.x * blockDim.x + threadIdx.x;
    if (i >= n4) return;
    float4 v = ((const float4*)in)[i];
    ((uint32_t*)hi)[2*i]   = pack2h(v.x, v.y);
    ((uint32_t*)hi)[2*i+1] = pack2h(v.z, v.w);
}

// W[K,N] fp32 -> Wt[N,K] fp16
__global__ void transpose_half_kernel(const float* __restrict__ W,
                                      __half* __restrict__ Th,
                                      int K, int N)
{
    __shared__ float t[32][33];
    int k0 = blockIdx.y * 32, n0 = blockIdx.x * 32;
    #pragma unroll
    for (int i = threadIdx.y; i < 32; i += 8)
        t[i][threadIdx.x] = W[(size_t)(k0 + i) * N + n0 + threadIdx.x];
    __syncthreads();
    #pragma unroll
    for (int i = threadIdx.y; i < 32; i += 8)
        Th[(size_t)(n0 + i) * K + k0 + threadIdx.x] = __float2half(t[threadIdx.x][i]);
}

// ---------------------------------------------------------------------------
// HMMA GEMM: C[M,N] = A[M,K] @ Bt[N,K]^T + bias   (fp16 x fp16, fp32 acc)
// CTA 128x128, 4 warps (2x2), warp tile 64x64, BK=64, 3-stage pipeline.
// 128 threads -> 256-reg budget at 2 CTAs/SM; ratio = 128 MMA / 32 ldsm per iter.
// ---------------------------------------------------------------------------
#define GM_BK    64
#define STAGES   3
#define TILE_B   16384                    // 128 rows x 128B
#define STAGE_B  (2 * TILE_B)             // A | B
#define GEMM_SMEM (STAGES * STAGE_B)      // 96 KB
#define OFF_A 0
#define OFF_B TILE_B

template<bool SPLIT>
__global__ __launch_bounds__(128, 2) void gemm_hmma(
    const __half* __restrict__ Ah,
    const __half* __restrict__ Bh,
    const float* __restrict__ bias, float* __restrict__ C,
    __half* __restrict__ Ch,
    int M, int N, int K)
{
    extern __shared__ char smc[];
    const uint32_t sb = smem_u32(smc);
    const int tid  = threadIdx.x;
    const int warp = tid >> 5, lane = tid & 31;
    const int wm = warp >> 1, wn = warp & 1;      // 2x2 warp grid, 64x64 tiles
    const int bm = blockIdx.y, bn = blockIdx.x;
    const int NC = K / GM_BK;                     // 32

    const __half* gA = Ah + (size_t)bm * 128 * K;
    const __half* gB = Bh + (size_t)bn * 128 * K;

    const int r0 = tid >> 3, c0 = tid & 7;        // 16 rows per pass, 8 chunks

    auto load_stage = [&](int chunk, int slot) {
        const int k0 = chunk * GM_BK;
        uint32_t base = sb + slot * STAGE_B;
        #pragma unroll
        for (int i = 0; i < 8; i++) {
            int r = r0 + i * 16;
            uint32_t so = gsw(r, c0);
            size_t go = (size_t)r * K + k0 + c0 * 8;
            cp_async16(base + OFF_A + so, gA + go);
            cp_async16(base + OFF_B + so, gB + go);
        }
        CP_COMMIT();
    };

    float acc[4][8][4];
    #pragma unroll
    for (int mt = 0; mt < 4; mt++)
        #pragma unroll
        for (int nt = 0; nt < 8; nt++)
            #pragma unroll
            for (int j = 0; j < 4; j++) acc[mt][nt][j] = 0.f;

    const int a_row = wm * 64 + (lane & 15);          // + mt*16
    const int a_cb  = (lane >> 4) & 1;
    const int b_row = wn * 64 + (lane & 7) + ((lane & 16) ? 8 : 0);  // + p*16
    const int b_cb  = (lane >> 3) & 1;

    #pragma unroll
    for (int s = 0; s < STAGES - 1; s++) load_stage(s, s);

    for (int c = 0; c < NC; c++) {
        if (c + STAGES - 1 < NC) { CP_WAIT(STAGES - 2); }
        else                     { CP_WAIT(0); }
        __syncthreads();
        if (c + STAGES - 1 < NC) load_stage(c + STAGES - 1, (c + STAGES - 1) % STAGES);

        const uint32_t base = sb + (c % STAGES) * STAGE_B;

        #pragma unroll
        for (int ks = 0; ks < 4; ks++) {
            uint32_t ahf[4][4];
            #pragma unroll
            for (int mt = 0; mt < 4; mt++)
                ldmx4(ahf[mt], base + OFF_A + gsw(a_row + mt * 16, 2 * ks + a_cb));
            uint32_t bhf[8][2];
            #pragma unroll
            for (int p = 0; p < 4; p++) {
                uint32_t r[4];
                ldmx4(r, base + OFF_B + gsw(b_row + p * 16, 2 * ks + b_cb));
                bhf[2*p][0] = r[0]; bhf[2*p][1] = r[1];
                bhf[2*p+1][0] = r[2]; bhf[2*p+1][1] = r[3];
            }
            #pragma unroll
            for (int mt = 0; mt < 4; mt++)
                #pragma unroll
                for (int nt = 0; nt < 8; nt++)
                    mma_fp16(acc[mt][nt], ahf[mt], bhf[nt]);
        }
    }

    const int erow = bm * 128 + wm * 64 + (lane >> 2);
    const int ecol = bn * 128 + wn * 64 + (lane & 3) * 2;
    #pragma unroll
    for (int mt = 0; mt < 4; mt++)
        #pragma unroll
        for (int nt = 0; nt < 8; nt++) {
            int col = ecol + nt * 8;
            float bx = bias[col], by = bias[col + 1];
            int ra = erow + mt * 16, rb = ra + 8;
            float v0 = acc[mt][nt][0] + bx, v1 = acc[mt][nt][1] + by;
            float v2 = acc[mt][nt][2] + bx, v3 = acc[mt][nt][3] + by;
            if (SPLIT) {
                *(uint32_t*)&Ch[(size_t)ra * N + col] = pack2h(v0, v1);
                *(uint32_t*)&Ch[(size_t)rb * N + col] = pack2h(v2, v3);
            } else {
                float2 o0 = {v0, v1}, o1 = {v2, v3};
                *(float2*)&C[(size_t)ra * N + col] = o0;
                *(float2*)&C[(size_t)rb * N + col] = o1;
            }
        }
}

// ---------------------------------------------------------------------------
// HMMA flash attention (unchanged from R11 — 17.7k MMA/us already)
// ---------------------------------------------------------------------------
#define AT_BQ 128
#define AT_BK 64
#define AT_NT (SEQ / AT_BK)          // 32
#define AQ_H 0
#define AST(s) (32768 + (s) * 32768)
#define AK_H 0
#define AV_H 16384
#define ATTN_SMEM (32768 + 2 * 32768)   // 96 KB

__global__ __launch_bounds__(256, 1) void attn_hmma(
    const __half* __restrict__ qkv_g,
    __half* __restrict__ oh_g)
{
    extern __shared__ char smc[];
    const uint32_t sb = smem_u32(smc);
    const int tid = threadIdx.x, warp = tid >> 5, lane = tid & 31;
    const int qt = blockIdx.x, bh = blockIdx.y;
    const int b = bh >> 4, h = bh & 15;
    const size_t tok0  = (size_t)b * SEQ + qt * AT_BQ;
    const size_t ktok0 = (size_t)b * SEQ;
    const int colQ = h * 3 * DK, colK = colQ + DK, colV = colQ + 2 * DK;
    const float SCALE = 0.08838834764831845f;

    auto loadQ = [&]() {
        #pragma unroll
        for (int i = 0; i < 8; i++) {
            int idx = tid + i * 256;
            int r = idx >> 4, ch = idx & 15;
            size_t g = (tok0 + r) * QKV_N + colQ + ch * 8;
            cp_async16(sb + AQ_H + asw(r, ch), qkv_g + g);
        }
        CP_COMMIT();
    };
    auto loadK = [&](int kt, int s) {
        #pragma unroll
        for (int i = 0; i < 4; i++) {
            int idx = tid + i * 256;
            int r = idx >> 4, ch = idx & 15;
            size_t g = (ktok0 + kt * AT_BK + r) * QKV_N + colK + ch * 8;
            cp_async16(sb + AST(s) + AK_H + asw(r, ch), qkv_g + g);
        }
        CP_COMMIT();
    };
    auto loadV = [&](int kt, int s) {
        #pragma unroll
        for (int i = 0; i < 4; i++) {
            int idx = tid + i * 256;
            int r = idx >> 4, ch = idx & 15;
            size_t g = (ktok0 + kt * AT_BK + r) * QKV_N + colV + ch * 8;
            cp_async16(sb + AST(s) + AV_H + asw(r, ch), qkv_g + g);
        }
        CP_COMMIT();
    };

    const int aq_row = warp * 16 + (lane & 15);
    const int a_cb   = lane >> 4;
    const int bk_row = (lane & 7) + ((lane & 16) ? 8 : 0);
    const int bk_cb  = (lane >> 3) & 1;
    const int v_row  = (lane & 7) + (((lane >> 3) & 1) << 3);
    const int v_cb   = lane >> 4;

    float oacc[16][4];
    #pragma unroll
    for (int n = 0; n < 16; n++)
        #pragma unroll
        for (int j = 0; j < 4; j++) oacc[n][j] = 0.f;
    float m0 = -1e30f, m1 = -1e30f, l0 = 0.f, l1 = 0.f;

    // prologue: Q, K0, V0, K1
    loadQ();
    loadK(0, 0);
    loadV(0, 0);
    loadK(1, 1);

    // hoist Q fragments into registers
    CP_WAIT(3);
    __syncthreads();
    uint32_t qfh[8][4];
    #pragma unroll
    for (int ks = 0; ks < 8; ks++)
        ldmx4(qfh[ks], sb + AQ_H + asw(aq_row, 2 * ks + a_cb));

    for (int kt = 0; kt < AT_NT; kt++) {
        const int cur = kt & 1;

        CP_WAIT(2);              // K_kt complete
        __syncthreads();
        loadV((kt + 1) % AT_NT, cur ^ 1);   // wrap-around keeps counts exact

        const uint32_t kb = sb + AST(cur);

        // ---- S = Q K^T ----
        float sacc[8][4];
        #pragma unroll
        for (int n = 0; n < 8; n++)
            #pragma unroll
            for (int j = 0; j < 4; j++) sacc[n][j] = 0.f;

        #pragma unroll
        for (int ks = 0; ks < 8; ks++) {
            #pragma unroll
            for (int p = 0; p < 4; p++) {
                uint32_t kh4[4];
                ldmx4(kh4, kb + AK_H + asw(p * 16 + bk_row, 2 * ks + bk_cb));
                mma_fp16(sacc[2*p],   qfh[ks], kh4);
                mma_fp16(sacc[2*p+1], qfh[ks], kh4 + 2);
            }
        }

        // ---- online softmax ----
        float mx0 = -1e30f, mx1 = -1e30f;
        #pragma unroll
        for (int n = 0; n < 8; n++) {
            sacc[n][0] *= SCALE; sacc[n][1] *= SCALE;
            sacc[n][2] *= SCALE; sacc[n][3] *= SCALE;
            mx0 = fmaxf(mx0, fmaxf(sacc[n][0], sacc[n][1]));
            mx1 = fmaxf(mx1, fmaxf(sacc[n][2], sacc[n][3]));
        }
        mx0 = fmaxf(mx0, __shfl_xor_sync(0xffffffffu, mx0, 1));
        mx0 = fmaxf(mx0, __shfl_xor_sync(0xffffffffu, mx0, 2));
        mx1 = fmaxf(mx1, __shfl_xor_sync(0xffffffffu, mx1, 1));
        mx1 = fmaxf(mx1, __shfl_xor_sync(0xffffffffu, mx1, 2));
        const float mn0 = fmaxf(m0, mx0), mn1 = fmaxf(m1, mx1);

        float sum0 = 0.f, sum1 = 0.f;
        uint32_t ph[8][2];
        #pragma unroll
        for (int n = 0; n < 8; n++) {
            float p00 = __expf(sacc[n][0] - mn0), p01 = __expf(sacc[n][1] - mn0);
            float p10 = __expf(sacc[n][2] - mn1), p11 = __expf(sacc[n][3] - mn1);
            sum0 += p00 + p01;
            sum1 += p10 + p11;
            ph[n][0] = pack2h(p00, p01);
            ph[n][1] = pack2h(p10, p11);
        }
        sum0 += __shfl_xor_sync(0xffffffffu, sum0, 1);
        sum0 += __shfl_xor_sync(0xffffffffu, sum0, 2);
        sum1 += __shfl_xor_sync(0xffffffffu, sum1, 1);
        sum1 += __shfl_xor_sync(0xffffffffu, sum1, 2);

        const float al0 = __expf(m0 - mn0), al1 = __expf(m1 - mn1);
        m0 = mn0; m1 = mn1;
        l0 = l0 * al0 + sum0;
        l1 = l1 * al1 + sum1;
        #pragma unroll
        for (int n = 0; n < 16; n++) {
            oacc[n][0] *= al0; oacc[n][1] *= al0;
            oacc[n][2] *= al1; oacc[n][3] *= al1;
        }

        CP_WAIT(2);              // V_kt complete
        __syncthreads();
        loadK((kt + 2) % AT_NT, cur);

        const uint32_t vb = sb + AST(cur);

        // ---- O += P V ----
        #pragma unroll
        for (int kk = 0; kk < 4; kk++) {
            uint32_t pah[4] = {ph[2*kk][0], ph[2*kk][1], ph[2*kk+1][0], ph[2*kk+1][1]};
            #pragma unroll
            for (int p = 0; p < 8; p++) {
                uint32_t vh4[4];
                ldmx4t(vh4, vb + AV_H + asw(kk * 16 + v_row, 2 * p + v_cb));
                mma_fp16(oacc[2*p],   pah, vh4);
                mma_fp16(oacc[2*p+1], pah, vh4 + 2);
            }
        }
    }

    // ---- epilogue: normalize, write fp16 ----
    const float inv0 = 1.f / l0, inv1 = 1.f / l1;
    const int rr = lane >> 2, c2 = (lane & 3) * 2;
    const size_t row0 = tok0 + warp * 16 + rr, row1 = row0 + 8;
    #pragma unroll
    for (int n = 0; n < 16; n++) {
        int col = h * DK + n * 8 + c2;
        *(uint32_t*)&oh_g[row0 * D_MODEL + col] = pack2h(oacc[n][0] * inv0, oacc[n][1] * inv0);
        *(uint32_t*)&oh_g[row1 * D_MODEL + col] = pack2h(oacc[n][2] * inv1, oacc[n][3] * inv1);
    }
}

// ---------------------------------------------------------------------------
extern "C" void kernel_launch(void* const* d_in, const int* in_sizes, int n_in,
                              void* d_out, int out_size)
{
    const float* x    = (const float*)d_in[0];
    const float* Wqkv = (const float*)d_in[1];
    const float* bqkv = (const float*)d_in[2];
    const float* Wout = (const float*)d_in[3];
    const float* bout = (const float*)d_in[4];
    float* out = (float*)d_out;

    __half *qkh, *ah, *wqh, *woh;
    cudaGetSymbolAddress((void**)&qkh, g_qkv_hi);
    cudaGetSymbolAddress((void**)&ah, g_a_hi);
    cudaGetSymbolAddress((void**)&wqh, g_wq_h);
    cudaGetSymbolAddress((void**)&woh, g_wo_h);

    cudaFuncSetAttribute((const void*)gemm_hmma<true>,
                         cudaFuncAttributeMaxDynamicSharedMemorySize, GEMM_SMEM);
    cudaFuncSetAttribute((const void*)gemm_hmma<false>,
                         cudaFuncAttributeMaxDynamicSharedMemorySize, GEMM_SMEM);
    cudaFuncSetAttribute(attn_hmma, cudaFuncAttributeMaxDynamicSharedMemorySize, ATTN_SMEM);

    {
        int n4 = ROWS * D_MODEL / 4;
        convert_half_kernel<<<(n4 + 255) / 256, 256>>>(x, ah, n4);
        transpose_half_kernel<<<dim3(QKV_N / 32, D_MODEL / 32), dim3(32, 8)>>>(
            Wqkv, wqh, D_MODEL, QKV_N);
        transpose_half_kernel<<<dim3(D_MODEL / 32, D_MODEL / 32), dim3(32, 8)>>>(
            Wout, woh, D_MODEL, D_MODEL);
    }

    // 1) QKV projection: fp16 output
    gemm_hmma<true><<<dim3(QKV_N / 128, ROWS / 128), 128, GEMM_SMEM>>>(
        ah, wqh, bqkv, nullptr, qkh, ROWS, QKV_N, D_MODEL);

    // 2) attention -> attn-out fp16
    attn_hmma<<<dim3(SEQ / AT_BQ, BATCH * NHEADS), 256, ATTN_SMEM>>>(qkh, ah);

    // 3) out-projection: fp32 output
    gemm_hmma<false><<<dim3(D_MODEL / 128, ROWS / 128), 128, GEMM_SMEM>>>(
        ah, woh, bout, out, nullptr, ROWS, D_MODEL, D_MODEL);
}